// round 7
// baseline (speedup 1.0000x reference)
#include <cuda_runtime.h>
#include <cuda_bf16.h>
#include <math.h>
#include <stdint.h>

#define DIMW 128
#define NG   100000
#define AS_B 272              // bytes per bf16 row (128*2 + 16 pad)

// ---------------- scratch (no allocs) ----------------
__device__ float g_pool[(size_t)NG * DIMW];
__device__ float g_pool2[(size_t)NG * DIMW];
__device__ float g_cnt[NG];
__device__ int   g_is64;
__device__ __nv_bfloat16 g_WTh[3 * 128 * 128];  // W{1,2,3}^T hi  [n][k]
__device__ __nv_bfloat16 g_WTl[3 * 128 * 128];  // lo

// ---------------- kAtom smem layout (bytes) ----------------
#define SM_GID   0             // int[2][128] = 1024
#define SM_B1    1024          // float[128]  = 512 (pad to 2048)
#define SM_W     2048          // Wh 34816 + Wl 34816 -> ends 71680
#define SM_BUF0  71680         // 69632 (A hi/lo OR sT 128*129*4=66048)
#define SM_BUF1  141312        // 69632 -> ends 210944
#define SMEM_ATOM 210944

// ---------------- kGraph smem layout ----------------
#define GS_C     0             // cnt / sV : 512B
#define GS_B     512           // bias     : 512B
#define GS_P     1024          // partials : 1024B
#define GS_W     2048          // 69632 -> ends 71680
#define GS_A     71680         // 69632 -> ends 141312
#define SMEM_GRAPH 141312

#define BAR384()    asm volatile("bar.sync 0, 384;" ::: "memory")
#define BAR_MMA()   asm volatile("bar.sync 1, 256;" ::: "memory")   // warps 0-7
#define BAR_IO()    asm volatile("bar.sync 2, 128;" ::: "memory")   // warps 8-11

__device__ __forceinline__ uint32_t smem_u32(const void* p) {
    uint32_t a;
    asm("{ .reg .u64 t; cvta.to.shared.u64 t, %1; cvt.u32.u64 %0, t; }" : "=r"(a) : "l"(p));
    return a;
}
__device__ __forceinline__ void ldsm4(uint32_t& r0, uint32_t& r1, uint32_t& r2, uint32_t& r3,
                                      uint32_t addr) {
    asm volatile("ldmatrix.sync.aligned.m8n8.x4.shared.b16 {%0,%1,%2,%3}, [%4];"
                 : "=r"(r0), "=r"(r1), "=r"(r2), "=r"(r3) : "r"(addr));
}
__device__ __forceinline__ void mma16816(float* c, const uint32_t* a, uint32_t b0, uint32_t b1) {
    asm volatile("mma.sync.aligned.m16n8k16.row.col.f32.bf16.bf16.f32 "
                 "{%0,%1,%2,%3}, {%4,%5,%6,%7}, {%8,%9}, {%0,%1,%2,%3};"
                 : "+f"(c[0]), "+f"(c[1]), "+f"(c[2]), "+f"(c[3])
                 : "r"(a[0]), "r"(a[1]), "r"(a[2]), "r"(a[3]), "r"(b0), "r"(b1));
}

// ---------------------------------------------------------------------------
// MMA warp core (warps 0..7): warp tile 32 rows x 64 cols, 3-pass bf16 split
// ---------------------------------------------------------------------------
__device__ __forceinline__ void lda8(uint32_t a[8][4], uint32_t Ab) {
    #pragma unroll
    for (int kk = 0; kk < 8; kk++)
        ldsm4(a[kk][0], a[kk][1], a[kk][2], a[kk][3], Ab + kk * 32);
}
__device__ __forceinline__ void inner_pass(const uint32_t a0[8][4], const uint32_t a1[8][4],
                                           uint32_t Bb, float acc[2][4][8]) {
    #pragma unroll
    for (int kk = 0; kk < 8; kk++) {
        uint32_t b[4][4];
        #pragma unroll
        for (int nb = 0; nb < 4; nb++)
            ldsm4(b[nb][0], b[nb][1], b[nb][2], b[nb][3], Bb + nb * 16 * AS_B + kk * 32);
        #pragma unroll
        for (int nb = 0; nb < 4; nb++) {
            mma16816(acc[0][nb],     a0[kk], b[nb][0], b[nb][1]);
            mma16816(acc[0][nb] + 4, a0[kk], b[nb][2], b[nb][3]);
            mma16816(acc[1][nb],     a1[kk], b[nb][0], b[nb][1]);
            mma16816(acc[1][nb] + 4, a1[kk], b[nb][2], b[nb][3]);
        }
    }
}
__device__ __forceinline__ void mma_tile(uint32_t A, uint32_t W, float acc[2][4][8]) {
    const int t = threadIdx.x, w = t >> 5, lane = t & 31;
    const int wm = w >> 1, wn = w & 1;
    const int lm = lane & 7, q = lane >> 3;
    const uint32_t aOff0 = (uint32_t)((wm * 32 + lm + (q & 1) * 8) * AS_B + ((q >> 1) * 8) * 2);
    const uint32_t aOff1 = aOff0 + 16 * AS_B;
    const uint32_t bOff  = (uint32_t)((wn * 64 + lm + (q >> 1) * 8) * AS_B + ((q & 1) * 8) * 2);
    uint32_t a0[8][4], a1[8][4];
    lda8(a0, A + aOff0);
    lda8(a1, A + aOff1);
    inner_pass(a0, a1, W + bOff, acc);           // Ah * Bh
    inner_pass(a0, a1, W + 34816 + bOff, acc);   // Ah * Bl
    lda8(a0, A + 34816 + aOff0);
    lda8(a1, A + 34816 + aOff1);
    inner_pass(a0, a1, W + bOff, acc);           // Al * Bh
}

// split one fp32 float4 into bf16 hi/lo and store at (row m, float4-col c)
__device__ __forceinline__ void split_store(float4 x, char* dstH, int m, int c) {
    __nv_bfloat16 h0 = __float2bfloat16_rn(x.x), h1 = __float2bfloat16_rn(x.y);
    __nv_bfloat16 h2 = __float2bfloat16_rn(x.z), h3 = __float2bfloat16_rn(x.w);
    __nv_bfloat162 hp0 = __halves2bfloat162(h0, h1);
    __nv_bfloat162 hp1 = __halves2bfloat162(h2, h3);
    __nv_bfloat162 lp0 = __halves2bfloat162(
        __float2bfloat16_rn(x.x - __bfloat162float(h0)),
        __float2bfloat16_rn(x.y - __bfloat162float(h1)));
    __nv_bfloat162 lp1 = __halves2bfloat162(
        __float2bfloat16_rn(x.z - __bfloat162float(h2)),
        __float2bfloat16_rn(x.w - __bfloat162float(h3)));
    *(uint2*)(dstH + m * AS_B + c * 8) = make_uint2(*(uint32_t*)&hp0, *(uint32_t*)&hp1);
    *(uint2*)(dstH + 34816 + m * AS_B + c * 8) = make_uint2(*(uint32_t*)&lp0, *(uint32_t*)&lp1);
}

// stage one prepped weight matrix into padded smem hi/lo (NT threads)
template <int NT>
__device__ __forceinline__ void stage_W(char* sm, uint32_t wOff, int widx, int t) {
    for (int i = t; i < 512; i += NT) {
        const int r = i >> 2, q = i & 3;
        const uint4* wh = (const uint4*)(g_WTh + widx * 16384 + r * 128 + q * 32);
        const uint4* wl = (const uint4*)(g_WTl + widx * 16384 + r * 128 + q * 32);
        char* dh = sm + wOff + r * AS_B + q * 64;
        char* dl = sm + wOff + 34816 + r * AS_B + q * 64;
        #pragma unroll
        for (int j = 0; j < 4; j++) {
            ((uint4*)dh)[j] = wh[j];
            ((uint4*)dl)[j] = wl[j];
        }
    }
}

// ---------------------------------------------------------------------------
__global__ void kZero(const int* __restrict__ batch32, int n) {
    size_t i = (size_t)blockIdx.x * blockDim.x + threadIdx.x;
    const size_t poolN = (size_t)NG * DIMW;
    if (i < poolN) g_pool[i] = 0.0f;
    else if (i < poolN + NG) g_cnt[i - poolN] = 0.0f;
    if (i == 0) g_is64 = (batch32[n - 1] == 0) ? 1 : 0;
}

__global__ void kPrep(const float* __restrict__ W1, const float* __restrict__ W2,
                      const float* __restrict__ W3) {
    int i = blockIdx.x * 256 + threadIdx.x;
    if (i < 3 * 16384) {
        int widx = i >> 14, e = i & 16383;
        int nn = e >> 7, kk = e & 127;
        const float* W = (widx == 0) ? W1 : (widx == 1) ? W2 : W3;
        float w = W[kk * 128 + nn];
        __nv_bfloat16 h = __float2bfloat16_rn(w);
        g_WTh[i] = h;
        g_WTl[i] = __float2bfloat16_rn(w - __bfloat162float(h));
    }
}

// ---------------------------------------------------------------------------
// IO-warp helpers for kAtomTC (tio = 0..127)
// ---------------------------------------------------------------------------
__device__ __forceinline__ void convert_tile(
    const float* __restrict__ feat, float* __restrict__ outFeat,
    const void* __restrict__ batch, int is64, long long n,
    long long tile, char* bufP, int* gidSlot, int tio)
{
    const int ww = tio >> 5, lane = tio & 31;
    #pragma unroll 4
    for (int j = 0; j < 32; j++) {
        const int m = ww * 32 + j;
        long long row = tile * 128 + m;
        float4 x = make_float4(0.f, 0.f, 0.f, 0.f);
        if (row < n) {
            x = ((const float4*)(feat + (size_t)row * 128))[lane];
            ((float4*)(outFeat + (size_t)row * 128))[lane] = x;
        }
        split_store(x, bufP, m, lane);
    }
    long long row = tile * 128 + tio;
    int g = -1;
    if (row < n)
        g = is64 ? (int)((const long long*)batch)[row] : ((const int*)batch)[row];
    gidSlot[tio] = g;
}

__device__ __forceinline__ void reduce_tile(const float* sT, const int* gid, int d)
{
    float run = 0.0f;
    int len = 0, cur = gid[0];
    for (int mm = 0; mm < 128; ++mm) {
        int g = gid[mm];
        if (g != cur) {
            if (cur >= 0) {
                atomicAdd(&g_pool[(size_t)cur * 128 + d], run);
                if (d == 0) atomicAdd(&g_cnt[cur], (float)len);
            }
            run = 0.0f; len = 0; cur = g;
        }
        if (g >= 0) { run += sT[d * 129 + mm]; len++; }
    }
    if (cur >= 0) {
        atomicAdd(&g_pool[(size_t)cur * 128 + d], run);
        if (d == 0) atomicAdd(&g_cnt[cur], (float)len);
    }
}

// ---------------------------------------------------------------------------
// kAtomTC: persistent, 384 threads, warp-specialized.
//   warps 0-7 : 3-pass bf16 mma + silu epilogue -> sT   (bar 1 internally)
//   warps 8-11: feat LDG + passthrough + bf16 split + gid + segment reduce
//               (bar 2 between reduce and convert)
// ---------------------------------------------------------------------------
__global__ void __launch_bounds__(384, 1) kAtomTC(
    const float* __restrict__ feat, const void* __restrict__ batch, int n,
    const float* __restrict__ b1, float* __restrict__ outFeat, int ntiles)
{
    extern __shared__ char sm[];
    const uint32_t smb = smem_u32(sm);
    const int t = threadIdx.x, w = t >> 5, lane = t & 31;
    const int is64 = g_is64;

    const int per = (ntiles + gridDim.x - 1) / gridDim.x;
    const int t0 = blockIdx.x * per;
    const int t1 = min(t0 + per, ntiles);
    if (t0 >= t1) return;
    const int nt = t1 - t0;

    if (t < 128) ((float*)(sm + SM_B1))[t] = b1[t];
    stage_W<384>(sm, SM_W, 0, t);
    BAR384();                                  // W + b1 visible

    if (w >= 8)
        convert_tile(feat, outFeat, batch, is64, n, t0,
                     sm + SM_BUF0, (int*)(sm + SM_GID), t - 256);

    for (int ii = 0; ii < nt; ii++) {
        BAR384();   // A(ii) ready; sT(ii-1) ready for reduce
        const int buf = ii & 1;
        char* bufP = sm + (buf ? SM_BUF1 : SM_BUF0);
        char* obufP = sm + (buf ? SM_BUF0 : SM_BUF1);

        if (w < 8) {
            // ---- MMA warps ----
            float acc[2][4][8];
            #pragma unroll
            for (int a = 0; a < 2; a++)
                #pragma unroll
                for (int b = 0; b < 4; b++)
                    #pragma unroll
                    for (int cjj = 0; cjj < 8; cjj++) acc[a][b][cjj] = 0.0f;
            mma_tile(smb + (buf ? SM_BUF1 : SM_BUF0), smb + SM_W, acc);

            BAR_MMA();   // ALL mma warps done reading A(buf) before sT overwrite

            // epilogue: bias + silu -> transposed sT (stride 129) in same buffer
            float* sT = (float*)bufP;
            const float* sB1 = (const float*)(sm + SM_B1);
            const int wm = w >> 1, wn = w & 1;
            #pragma unroll
            for (int mh = 0; mh < 2; mh++) {
                #pragma unroll
                for (int nb = 0; nb < 4; nb++) {
                    #pragma unroll
                    for (int g = 0; g < 2; g++) {
                        const int n0 = wn * 64 + nb * 16 + g * 8 + (lane & 3) * 2;
                        const int r0 = wm * 32 + mh * 16 + (lane >> 2);
                        #pragma unroll
                        for (int j = 0; j < 4; j++) {
                            const int nn = n0 + (j & 1);
                            const int mm = r0 + (j >> 1) * 8;
                            float x = acc[mh][nb][g * 4 + j] + sB1[nn];
                            sT[nn * 129 + mm] = x / (1.0f + __expf(-x));
                        }
                    }
                }
            }
        } else {
            // ---- IO warps ----
            const int tio = t - 256;
            if (ii > 0)
                reduce_tile((const float*)obufP,
                            (const int*)(sm + SM_GID) + (buf ^ 1) * 128, tio);
            BAR_IO();    // all IO threads done reading sT(ii-1) / gid before overwrite
            if (ii + 1 < nt)
                convert_tile(feat, outFeat, batch, is64, n, (long long)(t0 + ii + 1),
                             obufP, (int*)(sm + SM_GID) + (buf ^ 1) * 128, tio);
        }
    }

    BAR384();   // last sT ready
    if (w >= 8) {
        const int buf = (nt - 1) & 1;
        reduce_tile((const float*)(sm + (buf ? SM_BUF1 : SM_BUF0)),
                    (const int*)(sm + SM_GID) + buf * 128, t - 256);
    }
}

// ---------------------------------------------------------------------------
// kGraph warp-tile core (512 threads, 16 warps, warp tile 16x64)
// ---------------------------------------------------------------------------
__device__ __forceinline__ void mma_3pass_g(uint32_t aHi, uint32_t wHi, float acc[4][8]) {
    const int t = threadIdx.x;
    const int w = t >> 5, lane = t & 31;
    const int wm = w >> 1, wn = w & 1;
    const int lm = lane & 7, q = lane >> 3;
    const uint32_t aOff = (uint32_t)((wm * 16 + lm + (q & 1) * 8) * AS_B + ((q >> 1) * 8) * 2);
    const uint32_t bOff = (uint32_t)((wn * 64 + lm + (q >> 1) * 8) * AS_B + ((q & 1) * 8) * 2);
    uint32_t a[8][4];
    lda8(a, aHi + aOff);
    #pragma unroll
    for (int p = 0; p < 2; p++) {
        uint32_t Bb = (p == 0 ? wHi : wHi + 34816) + bOff;
        #pragma unroll
        for (int kk = 0; kk < 8; kk++) {
            uint32_t b[4][4];
            #pragma unroll
            for (int nb = 0; nb < 4; nb++)
                ldsm4(b[nb][0], b[nb][1], b[nb][2], b[nb][3], Bb + nb * 16 * AS_B + kk * 32);
            #pragma unroll
            for (int nb = 0; nb < 4; nb++) {
                mma16816(acc[nb],     a[kk], b[nb][0], b[nb][1]);
                mma16816(acc[nb] + 4, a[kk], b[nb][2], b[nb][3]);
            }
        }
    }
    lda8(a, aHi + 34816 + aOff);
    {
        uint32_t Bb = wHi + bOff;
        #pragma unroll
        for (int kk = 0; kk < 8; kk++) {
            uint32_t b[4][4];
            #pragma unroll
            for (int nb = 0; nb < 4; nb++)
                ldsm4(b[nb][0], b[nb][1], b[nb][2], b[nb][3], Bb + nb * 16 * AS_B + kk * 32);
            #pragma unroll
            for (int nb = 0; nb < 4; nb++) {
                mma16816(acc[nb],     a[kk], b[nb][0], b[nb][1]);
                mma16816(acc[nb] + 4, a[kk], b[nb][2], b[nb][3]);
            }
        }
    }
}

// ---------------------------------------------------------------------------
// kGraph1: g_pool2 = g_pool @ W2 + cnt * b2
// ---------------------------------------------------------------------------
__global__ void __launch_bounds__(512, 1) kGraph1(const float* __restrict__ b2)
{
    extern __shared__ char sm[];
    const uint32_t smb = smem_u32(sm);
    const int t = threadIdx.x, lane = t & 31, w = t >> 5;
    const int wm = w >> 1, wn = w & 1;
    const int a0 = blockIdx.x * 128;
    const int mb = t >> 5, c = t & 31;

    float* sCnt = (float*)(sm + GS_C);
    float* sB   = (float*)(sm + GS_B);
    if (t < 128) {
        sCnt[t] = (a0 + t < NG) ? g_cnt[a0 + t] : 0.0f;
        sB[t] = b2[t];
    }
    stage_W<512>(sm, GS_W, 1, t);
    #pragma unroll
    for (int j = 0; j < 8; j++) {
        const int m = mb + j * 16;
        int row = a0 + m;
        float4 x = (row < NG) ? ((const float4*)(g_pool + (size_t)row * 128))[c]
                              : make_float4(0.f, 0.f, 0.f, 0.f);
        split_store(x, sm + GS_A, m, c);
    }
    __syncthreads();

    float acc[4][8];
    #pragma unroll
    for (int a = 0; a < 4; a++)
        #pragma unroll
        for (int b = 0; b < 8; b++) acc[a][b] = 0.0f;
    mma_3pass_g(smb + GS_A, smb + GS_W, acc);

    #pragma unroll
    for (int nb = 0; nb < 4; nb++) {
        #pragma unroll
        for (int g = 0; g < 2; g++) {
            const int n0 = wn * 64 + nb * 16 + g * 8 + (lane & 3) * 2;
            const int mr = wm * 16 + (lane >> 2);
            int row0 = a0 + mr, row1 = a0 + mr + 8;
            if (row0 < NG) {
                float cn = sCnt[mr];
                *(float2*)(g_pool2 + (size_t)row0 * 128 + n0) =
                    make_float2(acc[nb][g*4+0] + cn * sB[n0], acc[nb][g*4+1] + cn * sB[n0+1]);
            }
            if (row1 < NG) {
                float cn = sCnt[mr + 8];
                *(float2*)(g_pool2 + (size_t)row1 * 128 + n0) =
                    make_float2(acc[nb][g*4+2] + cn * sB[n0], acc[nb][g*4+3] + cn * sB[n0+1]);
            }
        }
    }
}

// ---------------------------------------------------------------------------
// kGraph2: out = silu(g_pool2 @ W3 + b3) @ W4 + b4
// ---------------------------------------------------------------------------
__global__ void __launch_bounds__(512, 1) kGraph2(
    const float* __restrict__ b3, const float* __restrict__ W4,
    const float* __restrict__ b4, float* __restrict__ outS)
{
    extern __shared__ char sm[];
    const uint32_t smb = smem_u32(sm);
    const int t = threadIdx.x, lane = t & 31, w = t >> 5;
    const int wm = w >> 1, wn = w & 1;
    const int a0 = blockIdx.x * 128;
    const int mb = t >> 5, c = t & 31;

    float* sV = (float*)(sm + GS_C);
    float* sB = (float*)(sm + GS_B);
    float* sP = (float*)(sm + GS_P);   // partials [2][128]
    if (t < 128) { sV[t] = W4[t]; sB[t] = b3[t]; }
    stage_W<512>(sm, GS_W, 2, t);
    #pragma unroll
    for (int j = 0; j < 8; j++) {
        const int m = mb + j * 16;
        int row = a0 + m;
        float4 x = (row < NG) ? ((const float4*)(g_pool2 + (size_t)row * 128))[c]
                              : make_float4(0.f, 0.f, 0.f, 0.f);
        split_store(x, sm + GS_A, m, c);
    }
    __syncthreads();

    float acc[4][8];
    #pragma unroll
    for (int a = 0; a < 4; a++)
        #pragma unroll
        for (int b = 0; b < 8; b++) acc[a][b] = 0.0f;
    mma_3pass_g(smb + GS_A, smb + GS_W, acc);

    float s0 = 0.0f, s1 = 0.0f;
    #pragma unroll
    for (int nb = 0; nb < 4; nb++) {
        #pragma unroll
        for (int g = 0; g < 2; g++) {
            const int n0 = wn * 64 + nb * 16 + g * 8 + (lane & 3) * 2;
            #pragma unroll
            for (int j = 0; j < 4; j++) {
                const int nn = n0 + (j & 1);
                float x = acc[nb][g * 4 + j] + sB[nn];
                float h = x / (1.0f + __expf(-x));
                float p = h * sV[nn];
                if (j < 2) s0 += p; else s1 += p;
            }
        }
    }
    s0 += __shfl_xor_sync(0xFFFFFFFF, s0, 1);
    s0 += __shfl_xor_sync(0xFFFFFFFF, s0, 2);
    s1 += __shfl_xor_sync(0xFFFFFFFF, s1, 1);
    s1 += __shfl_xor_sync(0xFFFFFFFF, s1, 2);
    if ((lane & 3) == 0) {
        const int mr = wm * 16 + (lane >> 2);
        sP[wn * 128 + mr] = s0;
        sP[wn * 128 + mr + 8] = s1;
    }
    __syncthreads();
    if (t < 128) {
        int row = a0 + t;
        if (row < NG) outS[row] = sP[t] + sP[128 + t] + b4[0];
    }
}

// ---------------------------------------------------------------------------
extern "C" void kernel_launch(void* const* d_in, const int* in_sizes, int n_in,
                              void* d_out, int out_size)
{
    const float* feat  = (const float*)d_in[0];
    const void*  batch = d_in[1];
    const float* W1 = (const float*)d_in[2];
    const float* b1 = (const float*)d_in[3];
    const float* W2 = (const float*)d_in[4];
    const float* b2 = (const float*)d_in[5];
    const float* W3 = (const float*)d_in[6];
    const float* b3 = (const float*)d_in[7];
    const float* W4 = (const float*)d_in[8];
    const float* b4 = (const float*)d_in[9];

    const int n = in_sizes[0] / DIMW;
    float* outS    = (float*)d_out;
    float* outFeat = (float*)d_out + NG;

    cudaFuncSetAttribute(kAtomTC, cudaFuncAttributeMaxDynamicSharedMemorySize, SMEM_ATOM);
    cudaFuncSetAttribute(kGraph1, cudaFuncAttributeMaxDynamicSharedMemorySize, SMEM_GRAPH);
    cudaFuncSetAttribute(kGraph2, cudaFuncAttributeMaxDynamicSharedMemorySize, SMEM_GRAPH);

    {
        size_t total = (size_t)NG * DIMW + NG;
        kZero<<<(int)((total + 255) / 256), 256>>>((const int*)batch, n);
    }
    kPrep<<<192, 256>>>(W1, W2, W3);
    {
        int ntiles = (n + 127) / 128;
        kAtomTC<<<148, 384, SMEM_ATOM>>>(feat, batch, n, b1, outFeat, ntiles);
    }
    {
        int grid = (NG + 127) / 128;
        kGraph1<<<grid, 512, SMEM_GRAPH>>>(b2);
        kGraph2<<<grid, 512, SMEM_GRAPH>>>(b3, W4, b4, outS);
    }
}

// round 8
// speedup vs baseline: 1.5321x; 1.5321x over previous
#include <cuda_runtime.h>
#include <cuda_fp16.h>
#include <math.h>
#include <stdint.h>

#define DIMW 128
#define NG   100000
#define AS_B 272              // bytes per fp16 row (128*2 + 16 pad)

// ---------------- scratch (no allocs) ----------------
__device__ float g_pool[(size_t)NG * DIMW];
__device__ float g_pool2[(size_t)NG * DIMW];
__device__ float g_cnt[NG];
__device__ int   g_is64;
__device__ __half g_WTh[3 * 128 * 128];   // W{1,2,3}^T fp16  [n][k]

// ---------------- kAtom smem layout (bytes) ----------------
#define SM_GID   0             // int[128] = 512
#define SM_B1    512           // float[128] = 512
#define SM_W     1024          // W fp16: 34816 -> ends 35840
#define SM_A     35840         // Ah 34816 + Al 34816 -> ends 105472 (sT reuses: 66048)
#define SM_STAGE 105472        // fp32 tile 65536 -> ends 171008
#define SMEM_ATOM 171008

// ---------------- kGraph smem layout ----------------
#define GS_C     0             // cnt / sV : 512B
#define GS_B     512           // bias     : 512B
#define GS_P     1024          // partials : 1024B
#define GS_W     2048          // 34816 -> ends 36864
#define GS_A     36864         // 69632 -> ends 106496
#define SMEM_GRAPH 106496

__device__ __forceinline__ uint32_t smem_u32(const void* p) {
    uint32_t a;
    asm("{ .reg .u64 t; cvta.to.shared.u64 t, %1; cvt.u32.u64 %0, t; }" : "=r"(a) : "l"(p));
    return a;
}
__device__ __forceinline__ void ldsm4(uint32_t& r0, uint32_t& r1, uint32_t& r2, uint32_t& r3,
                                      uint32_t addr) {
    asm volatile("ldmatrix.sync.aligned.m8n8.x4.shared.b16 {%0,%1,%2,%3}, [%4];"
                 : "=r"(r0), "=r"(r1), "=r"(r2), "=r"(r3) : "r"(addr));
}
__device__ __forceinline__ void mma16816(float* c, const uint32_t* a, uint32_t b0, uint32_t b1) {
    asm volatile("mma.sync.aligned.m16n8k16.row.col.f32.f16.f16.f32 "
                 "{%0,%1,%2,%3}, {%4,%5,%6,%7}, {%8,%9}, {%0,%1,%2,%3};"
                 : "+f"(c[0]), "+f"(c[1]), "+f"(c[2]), "+f"(c[3])
                 : "r"(a[0]), "r"(a[1]), "r"(a[2]), "r"(a[3]), "r"(b0), "r"(b1));
}
__device__ __forceinline__ void cp16(uint32_t dst, const void* src, int sz) {
    asm volatile("cp.async.ca.shared.global [%0], [%1], 16, %2;"
                 :: "r"(dst), "l"(src), "r"(sz) : "memory");
}
__device__ __forceinline__ void cp_commit() { asm volatile("cp.async.commit_group;" ::: "memory"); }
__device__ __forceinline__ void cp_wait0()  { asm volatile("cp.async.wait_group 0;"  ::: "memory"); }

// ---------------------------------------------------------------------------
// 2-pass fp16-split warp-tile core: 16 rows x 64 cols per warp, 16 warps
// cover 128x128. D = Ah@Wh + Al@Wh (= A@Wh, exact in A).
// B loaded ONCE per k-step, reused for both A terms.
// ---------------------------------------------------------------------------
__device__ __forceinline__ void mma_2pass(uint32_t A, uint32_t W, float acc[4][8]) {
    const int t = threadIdx.x, w = t >> 5, lane = t & 31;
    const int wm = w >> 1, wn = w & 1;
    const int lm = lane & 7, q = lane >> 3;
    const uint32_t aOff = (uint32_t)((wm * 16 + lm + (q & 1) * 8) * AS_B + ((q >> 1) * 8) * 2);
    const uint32_t bOff = (uint32_t)((wn * 64 + lm + (q >> 1) * 8) * AS_B + ((q & 1) * 8) * 2);
    const uint32_t Ah = A + aOff, Al = A + 34816 + aOff, Bb = W + bOff;
    #pragma unroll
    for (int kk = 0; kk < 8; kk++) {
        uint32_t ah[4], al[4], b[4][4];
        ldsm4(ah[0], ah[1], ah[2], ah[3], Ah + kk * 32);
        ldsm4(al[0], al[1], al[2], al[3], Al + kk * 32);
        #pragma unroll
        for (int nb = 0; nb < 4; nb++)
            ldsm4(b[nb][0], b[nb][1], b[nb][2], b[nb][3], Bb + nb * 16 * AS_B + kk * 32);
        #pragma unroll
        for (int nb = 0; nb < 4; nb++) {
            mma16816(acc[nb],     ah, b[nb][0], b[nb][1]);
            mma16816(acc[nb] + 4, ah, b[nb][2], b[nb][3]);
        }
        #pragma unroll
        for (int nb = 0; nb < 4; nb++) {
            mma16816(acc[nb],     al, b[nb][0], b[nb][1]);
            mma16816(acc[nb] + 4, al, b[nb][2], b[nb][3]);
        }
    }
}

// stage one prepped fp16 weight matrix into padded smem (NT threads)
template <int NT>
__device__ __forceinline__ void stage_W(char* sm, uint32_t wOff, int widx, int t) {
    for (int i = t; i < 256; i += NT) {
        const int r = i >> 1, h = i & 1;
        const uint4* ws = (const uint4*)(g_WTh + widx * 16384 + r * 128 + h * 64);
        char* d = sm + wOff + r * AS_B + h * 128;
        #pragma unroll
        for (int j = 0; j < 8; j++) ((uint4*)d)[j] = ws[j];
    }
}

// split one fp32 float4 into fp16 hi/lo and store at (row m, float4-col c)
__device__ __forceinline__ void split_store(float4 x, char* dstH, int m, int c) {
    __half h0 = __float2half_rn(x.x), h1 = __float2half_rn(x.y);
    __half h2 = __float2half_rn(x.z), h3 = __float2half_rn(x.w);
    __half l0 = __float2half_rn(x.x - __half2float(h0));
    __half l1 = __float2half_rn(x.y - __half2float(h1));
    __half l2 = __float2half_rn(x.z - __half2float(h2));
    __half l3 = __float2half_rn(x.w - __half2float(h3));
    __half2 hp0 = __halves2half2(h0, h1), hp1 = __halves2half2(h2, h3);
    __half2 lp0 = __halves2half2(l0, l1), lp1 = __halves2half2(l2, l3);
    *(uint2*)(dstH + m * AS_B + c * 8) = make_uint2(*(uint32_t*)&hp0, *(uint32_t*)&hp1);
    *(uint2*)(dstH + 34816 + m * AS_B + c * 8) = make_uint2(*(uint32_t*)&lp0, *(uint32_t*)&lp1);
}

// ---------------------------------------------------------------------------
__global__ void kZero(const int* __restrict__ batch32, int n) {
    size_t i = (size_t)blockIdx.x * blockDim.x + threadIdx.x;
    const size_t poolN = (size_t)NG * DIMW;
    if (i < poolN) g_pool[i] = 0.0f;
    else if (i < poolN + NG) g_cnt[i - poolN] = 0.0f;
    if (i == 0) g_is64 = (batch32[n - 1] == 0) ? 1 : 0;
}

__global__ void kPrep(const float* __restrict__ W1, const float* __restrict__ W2,
                      const float* __restrict__ W3) {
    int i = blockIdx.x * 256 + threadIdx.x;
    if (i < 3 * 16384) {
        int widx = i >> 14, e = i & 16383;
        int nn = e >> 7, kk = e & 127;
        const float* W = (widx == 0) ? W1 : (widx == 1) ? W2 : W3;
        g_WTh[i] = __float2half_rn(W[kk * 128 + nn]);
    }
}

// ---------------------------------------------------------------------------
// kAtomTC: persistent, 512 threads (R4 structure, 2-pass fp16 core)
// ---------------------------------------------------------------------------
__device__ __forceinline__ void stage_tile(char* sm, const float* feat, long long tile,
                                           long long n, int t) {
    const int mb = t >> 5, c = t & 31;
    #pragma unroll
    for (int j = 0; j < 8; j++) {
        const int m = mb + j * 16;
        long long row = tile * 128 + m;
        uint32_t dst = smem_u32(sm + SM_STAGE + m * 512 + c * 16);
        const float* src = feat + (size_t)(row < n ? row : 0) * 128 + c * 4;
        cp16(dst, src, row < n ? 16 : 0);
    }
    cp_commit();
}

__global__ void __launch_bounds__(512, 1) kAtomTC(
    const float* __restrict__ feat, const void* __restrict__ batch, int n,
    const float* __restrict__ b1, float* __restrict__ outFeat, int ntiles)
{
    extern __shared__ char sm[];
    const uint32_t smb = smem_u32(sm);
    const int t = threadIdx.x, lane = t & 31, w = t >> 5;
    const int wm = w >> 1, wn = w & 1;
    const int is64 = g_is64;
    const int mb = t >> 5, c = t & 31;

    const int per = (ntiles + gridDim.x - 1) / gridDim.x;
    const int t0 = blockIdx.x * per;
    const int t1 = min(t0 + per, ntiles);
    if (t0 >= t1) return;

    stage_tile(sm, feat, t0, n, t);          // prologue cp.async
    if (t < 128) ((float*)(sm + SM_B1))[t] = b1[t];
    stage_W<512>(sm, SM_W, 0, t);
    cp_wait0();
    __syncthreads();

    for (int i = t0; i < t1; ++i) {
        const bool more = (i + 1 < t1);

        // 1) convert stage -> fp16 hi/lo + passthrough STG + gids
        #pragma unroll
        for (int j = 0; j < 8; j++) {
            const int m = mb + j * 16;
            float4 x = *(const float4*)(sm + SM_STAGE + m * 512 + c * 16);
            split_store(x, sm + SM_A, m, c);
            long long row = (long long)i * 128 + m;
            if (row < n) ((float4*)(outFeat + (size_t)row * 128))[c] = x;
        }
        if (t < 128) {
            long long row = (long long)i * 128 + t;
            int g = -1;
            if (row < n)
                g = is64 ? (int)((const long long*)batch)[row] : ((const int*)batch)[row];
            ((int*)(sm + SM_GID))[t] = g;
        }
        __syncthreads();

        // 2) prefetch next tile (overlaps mma)
        if (more) stage_tile(sm, feat, (long long)i + 1, n, t);

        // 3) mma
        float acc[4][8];
        #pragma unroll
        for (int a = 0; a < 4; a++)
            #pragma unroll
            for (int b = 0; b < 8; b++) acc[a][b] = 0.0f;
        mma_2pass(smb + SM_A, smb + SM_W, acc);
        __syncthreads();   // all warps done reading A

        // 4) epilogue: bias + silu -> transposed sT (stride 129) in A region
        float* sT = (float*)(sm + SM_A);
        const float* sB1 = (const float*)(sm + SM_B1);
        #pragma unroll
        for (int nb = 0; nb < 4; nb++) {
            #pragma unroll
            for (int g = 0; g < 2; g++) {
                const int n0 = wn * 64 + nb * 16 + g * 8 + (lane & 3) * 2;
                const int r0 = wm * 16 + (lane >> 2);
                #pragma unroll
                for (int j = 0; j < 4; j++) {
                    const int nn = n0 + (j & 1);
                    const int mm = r0 + (j >> 1) * 8;
                    float x = acc[nb][g * 4 + j] + sB1[nn];
                    sT[nn * 129 + mm] = x / (1.0f + __expf(-x));
                }
            }
        }
        cp_wait0();
        __syncthreads();

        // 5) run-length segment reduce (batch sorted); 4 quarters of 32 atoms
        const int d = t & 127, hh = t >> 7;
        const int mS = hh * 32, mE = mS + 32;
        const int* gid = (const int*)(sm + SM_GID);
        float run = 0.0f;
        int len = 0, cur = gid[mS];
        for (int mm = mS; mm < mE; ++mm) {
            int g = gid[mm];
            if (g != cur) {
                if (cur >= 0) {
                    atomicAdd(&g_pool[(size_t)cur * 128 + d], run);
                    if (d == 0) atomicAdd(&g_cnt[cur], (float)len);
                }
                run = 0.0f; len = 0; cur = g;
            }
            if (g >= 0) { run += sT[d * 129 + mm]; len++; }
        }
        if (cur >= 0) {
            atomicAdd(&g_pool[(size_t)cur * 128 + d], run);
            if (d == 0) atomicAdd(&g_cnt[cur], (float)len);
        }
        __syncthreads();   // reduce done before next convert overwrites sT/A
    }
}

// ---------------------------------------------------------------------------
// kGraph1: g_pool2 = g_pool @ W2 + cnt * b2   (512 threads, 128-row tiles)
// ---------------------------------------------------------------------------
__global__ void __launch_bounds__(512, 1) kGraph1(const float* __restrict__ b2)
{
    extern __shared__ char sm[];
    const uint32_t smb = smem_u32(sm);
    const int t = threadIdx.x, lane = t & 31, w = t >> 5;
    const int wm = w >> 1, wn = w & 1;
    const int a0 = blockIdx.x * 128;
    const int mb = t >> 5, c = t & 31;

    float* sCnt = (float*)(sm + GS_C);
    float* sB   = (float*)(sm + GS_B);
    if (t < 128) {
        sCnt[t] = (a0 + t < NG) ? g_cnt[a0 + t] : 0.0f;
        sB[t] = b2[t];
    }
    stage_W<512>(sm, GS_W, 1, t);
    #pragma unroll
    for (int j = 0; j < 8; j++) {
        const int m = mb + j * 16;
        int row = a0 + m;
        float4 x = (row < NG) ? ((const float4*)(g_pool + (size_t)row * 128))[c]
                              : make_float4(0.f, 0.f, 0.f, 0.f);
        split_store(x, sm + GS_A, m, c);
    }
    __syncthreads();

    float acc[4][8];
    #pragma unroll
    for (int a = 0; a < 4; a++)
        #pragma unroll
        for (int b = 0; b < 8; b++) acc[a][b] = 0.0f;
    mma_2pass(smb + GS_A, smb + GS_W, acc);

    #pragma unroll
    for (int nb = 0; nb < 4; nb++) {
        #pragma unroll
        for (int g = 0; g < 2; g++) {
            const int n0 = wn * 64 + nb * 16 + g * 8 + (lane & 3) * 2;
            const int mr = wm * 16 + (lane >> 2);
            int row0 = a0 + mr, row1 = a0 + mr + 8;
            if (row0 < NG) {
                float cn = sCnt[mr];
                *(float2*)(g_pool2 + (size_t)row0 * 128 + n0) =
                    make_float2(acc[nb][g*4+0] + cn * sB[n0], acc[nb][g*4+1] + cn * sB[n0+1]);
            }
            if (row1 < NG) {
                float cn = sCnt[mr + 8];
                *(float2*)(g_pool2 + (size_t)row1 * 128 + n0) =
                    make_float2(acc[nb][g*4+2] + cn * sB[n0], acc[nb][g*4+3] + cn * sB[n0+1]);
            }
        }
    }
}

// ---------------------------------------------------------------------------
// kGraph2: out = silu(g_pool2 @ W3 + b3) @ W4 + b4
// ---------------------------------------------------------------------------
__global__ void __launch_bounds__(512, 1) kGraph2(
    const float* __restrict__ b3, const float* __restrict__ W4,
    const float* __restrict__ b4, float* __restrict__ outS)
{
    extern __shared__ char sm[];
    const uint32_t smb = smem_u32(sm);
    const int t = threadIdx.x, lane = t & 31, w = t >> 5;
    const int wm = w >> 1, wn = w & 1;
    const int a0 = blockIdx.x * 128;
    const int mb = t >> 5, c = t & 31;

    float* sV = (float*)(sm + GS_C);
    float* sB = (float*)(sm + GS_B);
    float* sP = (float*)(sm + GS_P);   // partials [2][128]
    if (t < 128) { sV[t] = W4[t]; sB[t] = b3[t]; }
    stage_W<512>(sm, GS_W, 2, t);
    #pragma unroll
    for (int j = 0; j < 8; j++) {
        const int m = mb + j * 16;
        int row = a0 + m;
        float4 x = (row < NG) ? ((const float4*)(g_pool2 + (size_t)row * 128))[c]
                              : make_float4(0.f, 0.f, 0.f, 0.f);
        split_store(x, sm + GS_A, m, c);
    }
    __syncthreads();

    float acc[4][8];
    #pragma unroll
    for (int a = 0; a < 4; a++)
        #pragma unroll
        for (int b = 0; b < 8; b++) acc[a][b] = 0.0f;
    mma_2pass(smb + GS_A, smb + GS_W, acc);

    float s0 = 0.0f, s1 = 0.0f;
    #pragma unroll
    for (int nb = 0; nb < 4; nb++) {
        #pragma unroll
        for (int g = 0; g < 2; g++) {
            const int n0 = wn * 64 + nb * 16 + g * 8 + (lane & 3) * 2;
            #pragma unroll
            for (int j = 0; j < 4; j++) {
                const int nn = n0 + (j & 1);
                float x = acc[nb][g * 4 + j] + sB[nn];
                float h = x / (1.0f + __expf(-x));
                float p = h * sV[nn];
                if (j < 2) s0 += p; else s1 += p;
            }
        }
    }
    s0 += __shfl_xor_sync(0xFFFFFFFF, s0, 1);
    s0 += __shfl_xor_sync(0xFFFFFFFF, s0, 2);
    s1 += __shfl_xor_sync(0xFFFFFFFF, s1, 1);
    s1 += __shfl_xor_sync(0xFFFFFFFF, s1, 2);
    if ((lane & 3) == 0) {
        const int mr = wm * 16 + (lane >> 2);
        sP[wn * 128 + mr] = s0;
        sP[wn * 128 + mr + 8] = s1;
    }
    __syncthreads();
    if (t < 128) {
        int row = a0 + t;
        if (row < NG) outS[row] = sP[t] + sP[128 + t] + b4[0];
    }
}

// ---------------------------------------------------------------------------
extern "C" void kernel_launch(void* const* d_in, const int* in_sizes, int n_in,
                              void* d_out, int out_size)
{
    const float* feat  = (const float*)d_in[0];
    const void*  batch = d_in[1];
    const float* W1 = (const float*)d_in[2];
    const float* b1 = (const float*)d_in[3];
    const float* W2 = (const float*)d_in[4];
    const float* b2 = (const float*)d_in[5];
    const float* W3 = (const float*)d_in[6];
    const float* b3 = (const float*)d_in[7];
    const float* W4 = (const float*)d_in[8];
    const float* b4 = (const float*)d_in[9];

    const int n = in_sizes[0] / DIMW;
    float* outS    = (float*)d_out;
    float* outFeat = (float*)d_out + NG;

    cudaFuncSetAttribute(kAtomTC, cudaFuncAttributeMaxDynamicSharedMemorySize, SMEM_ATOM);
    cudaFuncSetAttribute(kGraph1, cudaFuncAttributeMaxDynamicSharedMemorySize, SMEM_GRAPH);
    cudaFuncSetAttribute(kGraph2, cudaFuncAttributeMaxDynamicSharedMemorySize, SMEM_GRAPH);

    {
        size_t total = (size_t)NG * DIMW + NG;
        kZero<<<(int)((total + 255) / 256), 256>>>((const int*)batch, n);
    }
    kPrep<<<192, 256>>>(W1, W2, W3);
    {
        int ntiles = (n + 127) / 128;
        kAtomTC<<<148, 512, SMEM_ATOM>>>(feat, batch, n, b1, outFeat, ntiles);
    }
    {
        int grid = (NG + 127) / 128;
        kGraph1<<<grid, 512, SMEM_GRAPH>>>(b2);
        kGraph2<<<grid, 512, SMEM_GRAPH>>>(b3, W4, b4, outS);
    }
}

// round 9
// speedup vs baseline: 1.6764x; 1.0942x over previous
#include <cuda_runtime.h>
#include <cuda_fp16.h>
#include <math.h>
#include <stdint.h>

#define DIMW 128
#define NG   100000
#define AS_B 272              // bytes per fp16 row (128*2 + 16 pad)

// ---------------- scratch (no allocs) ----------------
__device__ float g_pool[(size_t)NG * DIMW];
__device__ float g_pool2[(size_t)NG * DIMW];
__device__ float g_cnt[NG];
__device__ int   g_is64;
__device__ __half g_WTh[3 * 128 * 128];   // W{1,2,3}^T fp16  [n][k]

// ---------------- kAtom smem layout (bytes) ----------------
// A region kept 69632 wide: Ah occupies first 34816; sT (66048) reuses whole region
#define SM_GID   0             // int[128] = 512
#define SM_B1    512           // float[128] = 512
#define SM_W     1024          // W fp16: 34816 -> ends 35840
#define SM_A     35840         // Ah 34816 (+ sT spill space) -> ends 105472
#define SM_STAGE 105472        // fp32 tile 65536 -> ends 171008
#define SMEM_ATOM 171008

// ---------------- kGraph smem layout ----------------
#define GS_C     0             // cnt / sV : 512B
#define GS_B     512           // bias     : 512B
#define GS_P     1024          // partials : 1024B
#define GS_W     2048          // 34816 -> ends 36864
#define GS_A     36864         // Ah+Al 69632 -> ends 106496
#define SMEM_GRAPH 106496

__device__ __forceinline__ uint32_t smem_u32(const void* p) {
    uint32_t a;
    asm("{ .reg .u64 t; cvta.to.shared.u64 t, %1; cvt.u32.u64 %0, t; }" : "=r"(a) : "l"(p));
    return a;
}
__device__ __forceinline__ void ldsm4(uint32_t& r0, uint32_t& r1, uint32_t& r2, uint32_t& r3,
                                      uint32_t addr) {
    asm volatile("ldmatrix.sync.aligned.m8n8.x4.shared.b16 {%0,%1,%2,%3}, [%4];"
                 : "=r"(r0), "=r"(r1), "=r"(r2), "=r"(r3) : "r"(addr));
}
__device__ __forceinline__ void mma16816(float* c, const uint32_t* a, uint32_t b0, uint32_t b1) {
    asm volatile("mma.sync.aligned.m16n8k16.row.col.f32.f16.f16.f32 "
                 "{%0,%1,%2,%3}, {%4,%5,%6,%7}, {%8,%9}, {%0,%1,%2,%3};"
                 : "+f"(c[0]), "+f"(c[1]), "+f"(c[2]), "+f"(c[3])
                 : "r"(a[0]), "r"(a[1]), "r"(a[2]), "r"(a[3]), "r"(b0), "r"(b1));
}
__device__ __forceinline__ void cp16(uint32_t dst, const void* src, int sz) {
    asm volatile("cp.async.ca.shared.global [%0], [%1], 16, %2;"
                 :: "r"(dst), "l"(src), "r"(sz) : "memory");
}
__device__ __forceinline__ void cp_commit() { asm volatile("cp.async.commit_group;" ::: "memory"); }
__device__ __forceinline__ void cp_wait0()  { asm volatile("cp.async.wait_group 0;"  ::: "memory"); }

// ---------------------------------------------------------------------------
// Warp-tile cores: 16 rows x 64 cols per warp, 16 warps cover 128x128.
// ---------------------------------------------------------------------------
// 1-pass: D = Ah @ Wh (A and W both fp16-rounded) — used by kAtom
__device__ __forceinline__ void mma_1pass(uint32_t A, uint32_t W, float acc[4][8]) {
    const int t = threadIdx.x, w = t >> 5, lane = t & 31;
    const int wm = w >> 1, wn = w & 1;
    const int lm = lane & 7, q = lane >> 3;
    const uint32_t aOff = (uint32_t)((wm * 16 + lm + (q & 1) * 8) * AS_B + ((q >> 1) * 8) * 2);
    const uint32_t bOff = (uint32_t)((wn * 64 + lm + (q >> 1) * 8) * AS_B + ((q & 1) * 8) * 2);
    const uint32_t Ah = A + aOff, Bb = W + bOff;
    #pragma unroll
    for (int kk = 0; kk < 8; kk++) {
        uint32_t ah[4], b[4][4];
        ldsm4(ah[0], ah[1], ah[2], ah[3], Ah + kk * 32);
        #pragma unroll
        for (int nb = 0; nb < 4; nb++)
            ldsm4(b[nb][0], b[nb][1], b[nb][2], b[nb][3], Bb + nb * 16 * AS_B + kk * 32);
        #pragma unroll
        for (int nb = 0; nb < 4; nb++) {
            mma16816(acc[nb],     ah, b[nb][0], b[nb][1]);
            mma16816(acc[nb] + 4, ah, b[nb][2], b[nb][3]);
        }
    }
}
// 2-pass: D = (Ah + Al) @ Wh (exact A) — used by kGraph1/2
__device__ __forceinline__ void mma_2pass(uint32_t A, uint32_t W, float acc[4][8]) {
    const int t = threadIdx.x, w = t >> 5, lane = t & 31;
    const int wm = w >> 1, wn = w & 1;
    const int lm = lane & 7, q = lane >> 3;
    const uint32_t aOff = (uint32_t)((wm * 16 + lm + (q & 1) * 8) * AS_B + ((q >> 1) * 8) * 2);
    const uint32_t bOff = (uint32_t)((wn * 64 + lm + (q >> 1) * 8) * AS_B + ((q & 1) * 8) * 2);
    const uint32_t Ah = A + aOff, Al = A + 34816 + aOff, Bb = W + bOff;
    #pragma unroll
    for (int kk = 0; kk < 8; kk++) {
        uint32_t ah[4], al[4], b[4][4];
        ldsm4(ah[0], ah[1], ah[2], ah[3], Ah + kk * 32);
        ldsm4(al[0], al[1], al[2], al[3], Al + kk * 32);
        #pragma unroll
        for (int nb = 0; nb < 4; nb++)
            ldsm4(b[nb][0], b[nb][1], b[nb][2], b[nb][3], Bb + nb * 16 * AS_B + kk * 32);
        #pragma unroll
        for (int nb = 0; nb < 4; nb++) {
            mma16816(acc[nb],     ah, b[nb][0], b[nb][1]);
            mma16816(acc[nb] + 4, ah, b[nb][2], b[nb][3]);
        }
        #pragma unroll
        for (int nb = 0; nb < 4; nb++) {
            mma16816(acc[nb],     al, b[nb][0], b[nb][1]);
            mma16816(acc[nb] + 4, al, b[nb][2], b[nb][3]);
        }
    }
}

// stage one prepped fp16 weight matrix into padded smem (NT threads)
template <int NT>
__device__ __forceinline__ void stage_W(char* sm, uint32_t wOff, int widx, int t) {
    for (int i = t; i < 256; i += NT) {
        const int r = i >> 1, h = i & 1;
        const uint4* ws = (const uint4*)(g_WTh + widx * 16384 + r * 128 + h * 64);
        char* d = sm + wOff + r * AS_B + h * 128;
        #pragma unroll
        for (int j = 0; j < 8; j++) ((uint4*)d)[j] = ws[j];
    }
}

// fp16 round-only store (hi term) at (row m, float4-col c)
__device__ __forceinline__ void round_store(float4 x, char* dstH, int m, int c) {
    __half2 hp0 = __halves2half2(__float2half_rn(x.x), __float2half_rn(x.y));
    __half2 hp1 = __halves2half2(__float2half_rn(x.z), __float2half_rn(x.w));
    *(uint2*)(dstH + m * AS_B + c * 8) = make_uint2(*(uint32_t*)&hp0, *(uint32_t*)&hp1);
}
// fp16 hi/lo split store (exact A) at (row m, float4-col c)
__device__ __forceinline__ void split_store(float4 x, char* dstH, int m, int c) {
    __half h0 = __float2half_rn(x.x), h1 = __float2half_rn(x.y);
    __half h2 = __float2half_rn(x.z), h3 = __float2half_rn(x.w);
    __half l0 = __float2half_rn(x.x - __half2float(h0));
    __half l1 = __float2half_rn(x.y - __half2float(h1));
    __half l2 = __float2half_rn(x.z - __half2float(h2));
    __half l3 = __float2half_rn(x.w - __half2float(h3));
    __half2 hp0 = __halves2half2(h0, h1), hp1 = __halves2half2(h2, h3);
    __half2 lp0 = __halves2half2(l0, l1), lp1 = __halves2half2(l2, l3);
    *(uint2*)(dstH + m * AS_B + c * 8) = make_uint2(*(uint32_t*)&hp0, *(uint32_t*)&hp1);
    *(uint2*)(dstH + 34816 + m * AS_B + c * 8) = make_uint2(*(uint32_t*)&lp0, *(uint32_t*)&lp1);
}

// ---------------------------------------------------------------------------
__global__ void kZero(const int* __restrict__ batch32, int n) {
    size_t i = (size_t)blockIdx.x * blockDim.x + threadIdx.x;
    const size_t poolN = (size_t)NG * DIMW;
    if (i < poolN) g_pool[i] = 0.0f;
    else if (i < poolN + NG) g_cnt[i - poolN] = 0.0f;
    if (i == 0) g_is64 = (batch32[n - 1] == 0) ? 1 : 0;
}

__global__ void kPrep(const float* __restrict__ W1, const float* __restrict__ W2,
                      const float* __restrict__ W3) {
    int i = blockIdx.x * 256 + threadIdx.x;
    if (i < 3 * 16384) {
        int widx = i >> 14, e = i & 16383;
        int nn = e >> 7, kk = e & 127;
        const float* W = (widx == 0) ? W1 : (widx == 1) ? W2 : W3;
        g_WTh[i] = __float2half_rn(W[kk * 128 + nn]);
    }
}

// ---------------------------------------------------------------------------
// kAtomTC: persistent, 512 threads, 1-pass fp16 core
// ---------------------------------------------------------------------------
__device__ __forceinline__ void stage_tile(char* sm, const float* feat, long long tile,
                                           long long n, int t) {
    const int mb = t >> 5, c = t & 31;
    #pragma unroll
    for (int j = 0; j < 8; j++) {
        const int m = mb + j * 16;
        long long row = tile * 128 + m;
        uint32_t dst = smem_u32(sm + SM_STAGE + m * 512 + c * 16);
        const float* src = feat + (size_t)(row < n ? row : 0) * 128 + c * 4;
        cp16(dst, src, row < n ? 16 : 0);
    }
    cp_commit();
}

__global__ void __launch_bounds__(512, 1) kAtomTC(
    const float* __restrict__ feat, const void* __restrict__ batch, int n,
    const float* __restrict__ b1, float* __restrict__ outFeat, int ntiles)
{
    extern __shared__ char sm[];
    const uint32_t smb = smem_u32(sm);
    const int t = threadIdx.x, lane = t & 31, w = t >> 5;
    const int wm = w >> 1, wn = w & 1;
    const int is64 = g_is64;
    const int mb = t >> 5, c = t & 31;

    const int per = (ntiles + gridDim.x - 1) / gridDim.x;
    const int t0 = blockIdx.x * per;
    const int t1 = min(t0 + per, ntiles);
    if (t0 >= t1) return;

    stage_tile(sm, feat, t0, n, t);          // prologue cp.async
    if (t < 128) ((float*)(sm + SM_B1))[t] = b1[t];
    stage_W<512>(sm, SM_W, 0, t);
    cp_wait0();
    __syncthreads();

    for (int i = t0; i < t1; ++i) {
        const bool more = (i + 1 < t1);

        // 1) convert stage -> fp16 (round only) + passthrough STG + gids
        #pragma unroll
        for (int j = 0; j < 8; j++) {
            const int m = mb + j * 16;
            float4 x = *(const float4*)(sm + SM_STAGE + m * 512 + c * 16);
            round_store(x, sm + SM_A, m, c);
            long long row = (long long)i * 128 + m;
            if (row < n) ((float4*)(outFeat + (size_t)row * 128))[c] = x;
        }
        if (t < 128) {
            long long row = (long long)i * 128 + t;
            int g = -1;
            if (row < n)
                g = is64 ? (int)((const long long*)batch)[row] : ((const int*)batch)[row];
            ((int*)(sm + SM_GID))[t] = g;
        }
        __syncthreads();

        // 2) prefetch next tile (overlaps mma)
        if (more) stage_tile(sm, feat, (long long)i + 1, n, t);

        // 3) mma (1-pass)
        float acc[4][8];
        #pragma unroll
        for (int a = 0; a < 4; a++)
            #pragma unroll
            for (int b = 0; b < 8; b++) acc[a][b] = 0.0f;
        mma_1pass(smb + SM_A, smb + SM_W, acc);
        __syncthreads();   // all warps done reading A

        // 4) epilogue: bias + silu -> transposed sT (stride 129) in A region
        float* sT = (float*)(sm + SM_A);
        const float* sB1 = (const float*)(sm + SM_B1);
        #pragma unroll
        for (int nb = 0; nb < 4; nb++) {
            #pragma unroll
            for (int g = 0; g < 2; g++) {
                const int n0 = wn * 64 + nb * 16 + g * 8 + (lane & 3) * 2;
                const int r0 = wm * 16 + (lane >> 2);
                #pragma unroll
                for (int j = 0; j < 4; j++) {
                    const int nn = n0 + (j & 1);
                    const int mm = r0 + (j >> 1) * 8;
                    float x = acc[nb][g * 4 + j] + sB1[nn];
                    sT[nn * 129 + mm] = x / (1.0f + __expf(-x));
                }
            }
        }
        cp_wait0();
        __syncthreads();

        // 5) run-length segment reduce (batch sorted); 4 quarters of 32 atoms
        const int d = t & 127, hh = t >> 7;
        const int mS = hh * 32, mE = mS + 32;
        const int* gid = (const int*)(sm + SM_GID);
        float run = 0.0f;
        int len = 0, cur = gid[mS];
        for (int mm = mS; mm < mE; ++mm) {
            int g = gid[mm];
            if (g != cur) {
                if (cur >= 0) {
                    atomicAdd(&g_pool[(size_t)cur * 128 + d], run);
                    if (d == 0) atomicAdd(&g_cnt[cur], (float)len);
                }
                run = 0.0f; len = 0; cur = g;
            }
            if (g >= 0) { run += sT[d * 129 + mm]; len++; }
        }
        if (cur >= 0) {
            atomicAdd(&g_pool[(size_t)cur * 128 + d], run);
            if (d == 0) atomicAdd(&g_cnt[cur], (float)len);
        }
        __syncthreads();   // reduce done before next convert overwrites sT/A
    }
}

// ---------------------------------------------------------------------------
// kGraph1: g_pool2 = g_pool @ W2 + cnt * b2   (2-pass, exact A)
// ---------------------------------------------------------------------------
__global__ void __launch_bounds__(512, 1) kGraph1(const float* __restrict__ b2)
{
    extern __shared__ char sm[];
    const uint32_t smb = smem_u32(sm);
    const int t = threadIdx.x, lane = t & 31, w = t >> 5;
    const int wm = w >> 1, wn = w & 1;
    const int a0 = blockIdx.x * 128;
    const int mb = t >> 5, c = t & 31;

    float* sCnt = (float*)(sm + GS_C);
    float* sB   = (float*)(sm + GS_B);
    if (t < 128) {
        sCnt[t] = (a0 + t < NG) ? g_cnt[a0 + t] : 0.0f;
        sB[t] = b2[t];
    }
    stage_W<512>(sm, GS_W, 1, t);
    #pragma unroll
    for (int j = 0; j < 8; j++) {
        const int m = mb + j * 16;
        int row = a0 + m;
        float4 x = (row < NG) ? ((const float4*)(g_pool + (size_t)row * 128))[c]
                              : make_float4(0.f, 0.f, 0.f, 0.f);
        split_store(x, sm + GS_A, m, c);
    }
    __syncthreads();

    float acc[4][8];
    #pragma unroll
    for (int a = 0; a < 4; a++)
        #pragma unroll
        for (int b = 0; b < 8; b++) acc[a][b] = 0.0f;
    mma_2pass(smb + GS_A, smb + GS_W, acc);

    #pragma unroll
    for (int nb = 0; nb < 4; nb++) {
        #pragma unroll
        for (int g = 0; g < 2; g++) {
            const int n0 = wn * 64 + nb * 16 + g * 8 + (lane & 3) * 2;
            const int mr = wm * 16 + (lane >> 2);
            int row0 = a0 + mr, row1 = a0 + mr + 8;
            if (row0 < NG) {
                float cn = sCnt[mr];
                *(float2*)(g_pool2 + (size_t)row0 * 128 + n0) =
                    make_float2(acc[nb][g*4+0] + cn * sB[n0], acc[nb][g*4+1] + cn * sB[n0+1]);
            }
            if (row1 < NG) {
                float cn = sCnt[mr + 8];
                *(float2*)(g_pool2 + (size_t)row1 * 128 + n0) =
                    make_float2(acc[nb][g*4+2] + cn * sB[n0], acc[nb][g*4+3] + cn * sB[n0+1]);
            }
        }
    }
}

// ---------------------------------------------------------------------------
// kGraph2: out = silu(g_pool2 @ W3 + b3) @ W4 + b4   (2-pass, exact A)
// ---------------------------------------------------------------------------
__global__ void __launch_bounds__(512, 1) kGraph2(
    const float* __restrict__ b3, const float* __restrict__ W4,
    const float* __restrict__ b4, float* __restrict__ outS)
{
    extern __shared__ char sm[];
    const uint32_t smb = smem_u32(sm);
    const int t = threadIdx.x, lane = t & 31, w = t >> 5;
    const int wm = w >> 1, wn = w & 1;
    const int a0 = blockIdx.x * 128;
    const int mb = t >> 5, c = t & 31;

    float* sV = (float*)(sm + GS_C);
    float* sB = (float*)(sm + GS_B);
    float* sP = (float*)(sm + GS_P);   // partials [2][128]
    if (t < 128) { sV[t] = W4[t]; sB[t] = b3[t]; }
    stage_W<512>(sm, GS_W, 2, t);
    #pragma unroll
    for (int j = 0; j < 8; j++) {
        const int m = mb + j * 16;
        int row = a0 + m;
        float4 x = (row < NG) ? ((const float4*)(g_pool2 + (size_t)row * 128))[c]
                              : make_float4(0.f, 0.f, 0.f, 0.f);
        split_store(x, sm + GS_A, m, c);
    }
    __syncthreads();

    float acc[4][8];
    #pragma unroll
    for (int a = 0; a < 4; a++)
        #pragma unroll
        for (int b = 0; b < 8; b++) acc[a][b] = 0.0f;
    mma_2pass(smb + GS_A, smb + GS_W, acc);

    float s0 = 0.0f, s1 = 0.0f;
    #pragma unroll
    for (int nb = 0; nb < 4; nb++) {
        #pragma unroll
        for (int g = 0; g < 2; g++) {
            const int n0 = wn * 64 + nb * 16 + g * 8 + (lane & 3) * 2;
            #pragma unroll
            for (int j = 0; j < 4; j++) {
                const int nn = n0 + (j & 1);
                float x = acc[nb][g * 4 + j] + sB[nn];
                float h = x / (1.0f + __expf(-x));
                float p = h * sV[nn];
                if (j < 2) s0 += p; else s1 += p;
            }
        }
    }
    s0 += __shfl_xor_sync(0xFFFFFFFF, s0, 1);
    s0 += __shfl_xor_sync(0xFFFFFFFF, s0, 2);
    s1 += __shfl_xor_sync(0xFFFFFFFF, s1, 1);
    s1 += __shfl_xor_sync(0xFFFFFFFF, s1, 2);
    if ((lane & 3) == 0) {
        const int mr = wm * 16 + (lane >> 2);
        sP[wn * 128 + mr] = s0;
        sP[wn * 128 + mr + 8] = s1;
    }
    __syncthreads();
    if (t < 128) {
        int row = a0 + t;
        if (row < NG) outS[row] = sP[t] + sP[128 + t] + b4[0];
    }
}

// ---------------------------------------------------------------------------
extern "C" void kernel_launch(void* const* d_in, const int* in_sizes, int n_in,
                              void* d_out, int out_size)
{
    const float* feat  = (const float*)d_in[0];
    const void*  batch = d_in[1];
    const float* W1 = (const float*)d_in[2];
    const float* b1 = (const float*)d_in[3];
    const float* W2 = (const float*)d_in[4];
    const float* b2 = (const float*)d_in[5];
    const float* W3 = (const float*)d_in[6];
    const float* b3 = (const float*)d_in[7];
    const float* W4 = (const float*)d_in[8];
    const float* b4 = (const float*)d_in[9];

    const int n = in_sizes[0] / DIMW;
    float* outS    = (float*)d_out;
    float* outFeat = (float*)d_out + NG;

    cudaFuncSetAttribute(kAtomTC, cudaFuncAttributeMaxDynamicSharedMemorySize, SMEM_ATOM);
    cudaFuncSetAttribute(kGraph1, cudaFuncAttributeMaxDynamicSharedMemorySize, SMEM_GRAPH);
    cudaFuncSetAttribute(kGraph2, cudaFuncAttributeMaxDynamicSharedMemorySize, SMEM_GRAPH);

    {
        size_t total = (size_t)NG * DIMW + NG;
        kZero<<<(int)((total + 255) / 256), 256>>>((const int*)batch, n);
    }
    kPrep<<<192, 256>>>(W1, W2, W3);
    {
        int ntiles = (n + 127) / 128;
        kAtomTC<<<148, 512, SMEM_ATOM>>>(feat, batch, n, b1, outFeat, ntiles);
    }
    {
        int grid = (NG + 127) / 128;
        kGraph1<<<grid, 512, SMEM_GRAPH>>>(b2);
        kGraph2<<<grid, 512, SMEM_GRAPH>>>(b3, W4, b4, outS);
    }
}

// round 10
// speedup vs baseline: 2.1085x; 1.2578x over previous
#include <cuda_runtime.h>
#include <cuda_fp16.h>
#include <math.h>
#include <stdint.h>

#define DIMW 128
#define NG   100000
#define AS_B 272              // bytes per fp16 row (128*2 + 16 pad)

// ---------------- scratch (no allocs) ----------------
__device__ float g_pool[(size_t)NG * DIMW];
__device__ float g_pool2[(size_t)NG * DIMW];
__device__ float g_cnt[NG];
__device__ int   g_is64;
__device__ __half g_WTh[3 * 128 * 128];   // W{1,2,3}^T fp16  [n][k]

// ---------------- kAtom smem layout (bytes) ----------------
// No fp32 stage: direct LDG in convert phase; 2 CTAs/SM co-residency hides latency.
#define SM_GID   0             // int[128] = 512
#define SM_B1    512           // float[128] = 512
#define SM_W     1024          // W fp16: 34816 -> ends 35840
#define SM_A     35840         // Ah 34816 ; sT (66048) reuses region -> ends 105472
#define SMEM_ATOM 105472

// ---------------- kGraph smem layout ----------------
#define GS_C     0             // cnt / sV : 512B
#define GS_B     512           // bias     : 512B
#define GS_P     1024          // partials : 1024B
#define GS_W     2048          // 34816 -> ends 36864
#define GS_A     36864         // Ah+Al 69632 -> ends 106496
#define SMEM_GRAPH 106496

__device__ __forceinline__ uint32_t smem_u32(const void* p) {
    uint32_t a;
    asm("{ .reg .u64 t; cvta.to.shared.u64 t, %1; cvt.u32.u64 %0, t; }" : "=r"(a) : "l"(p));
    return a;
}
__device__ __forceinline__ void ldsm4(uint32_t& r0, uint32_t& r1, uint32_t& r2, uint32_t& r3,
                                      uint32_t addr) {
    asm volatile("ldmatrix.sync.aligned.m8n8.x4.shared.b16 {%0,%1,%2,%3}, [%4];"
                 : "=r"(r0), "=r"(r1), "=r"(r2), "=r"(r3) : "r"(addr));
}
__device__ __forceinline__ void mma16816(float* c, const uint32_t* a, uint32_t b0, uint32_t b1) {
    asm volatile("mma.sync.aligned.m16n8k16.row.col.f32.f16.f16.f32 "
                 "{%0,%1,%2,%3}, {%4,%5,%6,%7}, {%8,%9}, {%0,%1,%2,%3};"
                 : "+f"(c[0]), "+f"(c[1]), "+f"(c[2]), "+f"(c[3])
                 : "r"(a[0]), "r"(a[1]), "r"(a[2]), "r"(a[3]), "r"(b0), "r"(b1));
}

// ---------------------------------------------------------------------------
// Warp-tile cores: 16 rows x 64 cols per warp, 16 warps cover 128x128.
// ---------------------------------------------------------------------------
// 1-pass: D = Ah @ Wh — used by kAtom
__device__ __forceinline__ void mma_1pass(uint32_t A, uint32_t W, float acc[4][8]) {
    const int t = threadIdx.x, w = t >> 5, lane = t & 31;
    const int wm = w >> 1, wn = w & 1;
    const int lm = lane & 7, q = lane >> 3;
    const uint32_t aOff = (uint32_t)((wm * 16 + lm + (q & 1) * 8) * AS_B + ((q >> 1) * 8) * 2);
    const uint32_t bOff = (uint32_t)((wn * 64 + lm + (q >> 1) * 8) * AS_B + ((q & 1) * 8) * 2);
    const uint32_t Ah = A + aOff, Bb = W + bOff;
    #pragma unroll
    for (int kk = 0; kk < 8; kk++) {
        uint32_t ah[4], b[4][4];
        ldsm4(ah[0], ah[1], ah[2], ah[3], Ah + kk * 32);
        #pragma unroll
        for (int nb = 0; nb < 4; nb++)
            ldsm4(b[nb][0], b[nb][1], b[nb][2], b[nb][3], Bb + nb * 16 * AS_B + kk * 32);
        #pragma unroll
        for (int nb = 0; nb < 4; nb++) {
            mma16816(acc[nb],     ah, b[nb][0], b[nb][1]);
            mma16816(acc[nb] + 4, ah, b[nb][2], b[nb][3]);
        }
    }
}
// 2-pass: D = (Ah + Al) @ Wh (exact A) — used by kGraph1/2
__device__ __forceinline__ void mma_2pass(uint32_t A, uint32_t W, float acc[4][8]) {
    const int t = threadIdx.x, w = t >> 5, lane = t & 31;
    const int wm = w >> 1, wn = w & 1;
    const int lm = lane & 7, q = lane >> 3;
    const uint32_t aOff = (uint32_t)((wm * 16 + lm + (q & 1) * 8) * AS_B + ((q >> 1) * 8) * 2);
    const uint32_t bOff = (uint32_t)((wn * 64 + lm + (q >> 1) * 8) * AS_B + ((q & 1) * 8) * 2);
    const uint32_t Ah = A + aOff, Al = A + 34816 + aOff, Bb = W + bOff;
    #pragma unroll
    for (int kk = 0; kk < 8; kk++) {
        uint32_t ah[4], al[4], b[4][4];
        ldsm4(ah[0], ah[1], ah[2], ah[3], Ah + kk * 32);
        ldsm4(al[0], al[1], al[2], al[3], Al + kk * 32);
        #pragma unroll
        for (int nb = 0; nb < 4; nb++)
            ldsm4(b[nb][0], b[nb][1], b[nb][2], b[nb][3], Bb + nb * 16 * AS_B + kk * 32);
        #pragma unroll
        for (int nb = 0; nb < 4; nb++) {
            mma16816(acc[nb],     ah, b[nb][0], b[nb][1]);
            mma16816(acc[nb] + 4, ah, b[nb][2], b[nb][3]);
        }
        #pragma unroll
        for (int nb = 0; nb < 4; nb++) {
            mma16816(acc[nb],     al, b[nb][0], b[nb][1]);
            mma16816(acc[nb] + 4, al, b[nb][2], b[nb][3]);
        }
    }
}

// stage one prepped fp16 weight matrix into padded smem (NT threads)
template <int NT>
__device__ __forceinline__ void stage_W(char* sm, uint32_t wOff, int widx, int t) {
    for (int i = t; i < 256; i += NT) {
        const int r = i >> 1, h = i & 1;
        const uint4* ws = (const uint4*)(g_WTh + widx * 16384 + r * 128 + h * 64);
        char* d = sm + wOff + r * AS_B + h * 128;
        #pragma unroll
        for (int j = 0; j < 8; j++) ((uint4*)d)[j] = ws[j];
    }
}

// fp16 round-only store (hi term) at (row m, float4-col c)
__device__ __forceinline__ void round_store(float4 x, char* dstH, int m, int c) {
    __half2 hp0 = __halves2half2(__float2half_rn(x.x), __float2half_rn(x.y));
    __half2 hp1 = __halves2half2(__float2half_rn(x.z), __float2half_rn(x.w));
    *(uint2*)(dstH + m * AS_B + c * 8) = make_uint2(*(uint32_t*)&hp0, *(uint32_t*)&hp1);
}
// fp16 hi/lo split store (exact A) at (row m, float4-col c)
__device__ __forceinline__ void split_store(float4 x, char* dstH, int m, int c) {
    __half h0 = __float2half_rn(x.x), h1 = __float2half_rn(x.y);
    __half h2 = __float2half_rn(x.z), h3 = __float2half_rn(x.w);
    __half l0 = __float2half_rn(x.x - __half2float(h0));
    __half l1 = __float2half_rn(x.y - __half2float(h1));
    __half l2 = __float2half_rn(x.z - __half2float(h2));
    __half l3 = __float2half_rn(x.w - __half2float(h3));
    __half2 hp0 = __halves2half2(h0, h1), hp1 = __halves2half2(h2, h3);
    __half2 lp0 = __halves2half2(l0, l1), lp1 = __halves2half2(l2, l3);
    *(uint2*)(dstH + m * AS_B + c * 8) = make_uint2(*(uint32_t*)&hp0, *(uint32_t*)&hp1);
    *(uint2*)(dstH + 34816 + m * AS_B + c * 8) = make_uint2(*(uint32_t*)&lp0, *(uint32_t*)&lp1);
}

// ---------------------------------------------------------------------------
__global__ void kZero(const int* __restrict__ batch32, int n) {
    size_t i = (size_t)blockIdx.x * blockDim.x + threadIdx.x;
    const size_t pool4 = (size_t)NG * DIMW / 4;
    if (i < pool4)
        ((float4*)g_pool)[i] = make_float4(0.f, 0.f, 0.f, 0.f);
    else if (i < pool4 + NG)
        g_cnt[i - pool4] = 0.0f;
    if (i == 0) g_is64 = (batch32[n - 1] == 0) ? 1 : 0;
}

__global__ void kPrep(const float* __restrict__ W1, const float* __restrict__ W2,
                      const float* __restrict__ W3) {
    int i = blockIdx.x * 256 + threadIdx.x;
    if (i < 3 * 16384) {
        int widx = i >> 14, e = i & 16383;
        int nn = e >> 7, kk = e & 127;
        const float* W = (widx == 0) ? W1 : (widx == 1) ? W2 : W3;
        g_WTh[i] = __float2half_rn(W[kk * 128 + nn]);
    }
}

// ---------------------------------------------------------------------------
// kAtomTC: persistent, 512 threads, 2 CTAs/SM, 1-pass fp16 core.
// Direct LDG in convert phase; co-resident CTA's mma hides memory latency.
// ---------------------------------------------------------------------------
__global__ void __launch_bounds__(512, 2) kAtomTC(
    const float* __restrict__ feat, const void* __restrict__ batch, int n,
    const float* __restrict__ b1, float* __restrict__ outFeat, int ntiles)
{
    extern __shared__ char sm[];
    const uint32_t smb = smem_u32(sm);
    const int t = threadIdx.x, lane = t & 31, w = t >> 5;
    const int wm = w >> 1, wn = w & 1;
    const int is64 = g_is64;
    const int mb = t >> 5, c = t & 31;

    const int per = (ntiles + gridDim.x - 1) / gridDim.x;
    const int t0 = blockIdx.x * per;
    const int t1 = min(t0 + per, ntiles);
    if (t0 >= t1) return;

    if (t < 128) ((float*)(sm + SM_B1))[t] = b1[t];
    stage_W<512>(sm, SM_W, 0, t);
    __syncthreads();

    for (int i = t0; i < t1; ++i) {
        // 1) convert: direct LDG -> fp16 round -> STS ; passthrough STG ; gids
        #pragma unroll
        for (int j = 0; j < 8; j++) {
            const int m = mb + j * 16;
            long long row = (long long)i * 128 + m;
            float4 x = make_float4(0.f, 0.f, 0.f, 0.f);
            if (row < n) {
                x = ((const float4*)(feat + (size_t)row * 128))[c];
                ((float4*)(outFeat + (size_t)row * 128))[c] = x;
            }
            round_store(x, sm + SM_A, m, c);
        }
        if (t < 128) {
            long long row = (long long)i * 128 + t;
            int g = -1;
            if (row < n)
                g = is64 ? (int)((const long long*)batch)[row] : ((const int*)batch)[row];
            ((int*)(sm + SM_GID))[t] = g;
        }
        __syncthreads();

        // 2) mma (1-pass)
        float acc[4][8];
        #pragma unroll
        for (int a = 0; a < 4; a++)
            #pragma unroll
            for (int b = 0; b < 8; b++) acc[a][b] = 0.0f;
        mma_1pass(smb + SM_A, smb + SM_W, acc);
        __syncthreads();   // all warps done reading A

        // 3) epilogue: bias + silu -> transposed sT (stride 129) in A region
        float* sT = (float*)(sm + SM_A);
        const float* sB1 = (const float*)(sm + SM_B1);
        #pragma unroll
        for (int nb = 0; nb < 4; nb++) {
            #pragma unroll
            for (int g = 0; g < 2; g++) {
                const int n0 = wn * 64 + nb * 16 + g * 8 + (lane & 3) * 2;
                const int r0 = wm * 16 + (lane >> 2);
                #pragma unroll
                for (int j = 0; j < 4; j++) {
                    const int nn = n0 + (j & 1);
                    const int mm = r0 + (j >> 1) * 8;
                    float x = acc[nb][g * 4 + j] + sB1[nn];
                    sT[nn * 129 + mm] = x / (1.0f + __expf(-x));
                }
            }
        }
        __syncthreads();

        // 4) run-length segment reduce (batch sorted); 4 quarters of 32 atoms
        const int d = t & 127, hh = t >> 7;
        const int mS = hh * 32, mE = mS + 32;
        const int* gid = (const int*)(sm + SM_GID);
        float run = 0.0f;
        int len = 0, cur = gid[mS];
        for (int mm = mS; mm < mE; ++mm) {
            int g = gid[mm];
            if (g != cur) {
                if (cur >= 0) {
                    atomicAdd(&g_pool[(size_t)cur * 128 + d], run);
                    if (d == 0) atomicAdd(&g_cnt[cur], (float)len);
                }
                run = 0.0f; len = 0; cur = g;
            }
            if (g >= 0) { run += sT[d * 129 + mm]; len++; }
        }
        if (cur >= 0) {
            atomicAdd(&g_pool[(size_t)cur * 128 + d], run);
            if (d == 0) atomicAdd(&g_cnt[cur], (float)len);
        }
        __syncthreads();   // reduce done before next convert overwrites sT/A
    }
}

// ---------------------------------------------------------------------------
// kGraph1: g_pool2 = g_pool @ W2 + cnt * b2   (2-pass, exact A)
// ---------------------------------------------------------------------------
__global__ void __launch_bounds__(512, 1) kGraph1(const float* __restrict__ b2)
{
    extern __shared__ char sm[];
    const uint32_t smb = smem_u32(sm);
    const int t = threadIdx.x, lane = t & 31, w = t >> 5;
    const int wm = w >> 1, wn = w & 1;
    const int a0 = blockIdx.x * 128;
    const int mb = t >> 5, c = t & 31;

    float* sCnt = (float*)(sm + GS_C);
    float* sB   = (float*)(sm + GS_B);
    if (t < 128) {
        sCnt[t] = (a0 + t < NG) ? g_cnt[a0 + t] : 0.0f;
        sB[t] = b2[t];
    }
    stage_W<512>(sm, GS_W, 1, t);
    #pragma unroll
    for (int j = 0; j < 8; j++) {
        const int m = mb + j * 16;
        int row = a0 + m;
        float4 x = (row < NG) ? ((const float4*)(g_pool + (size_t)row * 128))[c]
                              : make_float4(0.f, 0.f, 0.f, 0.f);
        split_store(x, sm + GS_A, m, c);
    }
    __syncthreads();

    float acc[4][8];
    #pragma unroll
    for (int a = 0; a < 4; a++)
        #pragma unroll
        for (int b = 0; b < 8; b++) acc[a][b] = 0.0f;
    mma_2pass(smb + GS_A, smb + GS_W, acc);

    #pragma unroll
    for (int nb = 0; nb < 4; nb++) {
        #pragma unroll
        for (int g = 0; g < 2; g++) {
            const int n0 = wn * 64 + nb * 16 + g * 8 + (lane & 3) * 2;
            const int mr = wm * 16 + (lane >> 2);
            int row0 = a0 + mr, row1 = a0 + mr + 8;
            if (row0 < NG) {
                float cn = sCnt[mr];
                *(float2*)(g_pool2 + (size_t)row0 * 128 + n0) =
                    make_float2(acc[nb][g*4+0] + cn * sB[n0], acc[nb][g*4+1] + cn * sB[n0+1]);
            }
            if (row1 < NG) {
                float cn = sCnt[mr + 8];
                *(float2*)(g_pool2 + (size_t)row1 * 128 + n0) =
                    make_float2(acc[nb][g*4+2] + cn * sB[n0], acc[nb][g*4+3] + cn * sB[n0+1]);
            }
        }
    }
}

// ---------------------------------------------------------------------------
// kGraph2: out = silu(g_pool2 @ W3 + b3) @ W4 + b4   (2-pass, exact A)
// ---------------------------------------------------------------------------
__global__ void __launch_bounds__(512, 1) kGraph2(
    const float* __restrict__ b3, const float* __restrict__ W4,
    const float* __restrict__ b4, float* __restrict__ outS)
{
    extern __shared__ char sm[];
    const uint32_t smb = smem_u32(sm);
    const int t = threadIdx.x, lane = t & 31, w = t >> 5;
    const int wm = w >> 1, wn = w & 1;
    const int a0 = blockIdx.x * 128;
    const int mb = t >> 5, c = t & 31;

    float* sV = (float*)(sm + GS_C);
    float* sB = (float*)(sm + GS_B);
    float* sP = (float*)(sm + GS_P);   // partials [2][128]
    if (t < 128) { sV[t] = W4[t]; sB[t] = b3[t]; }
    stage_W<512>(sm, GS_W, 2, t);
    #pragma unroll
    for (int j = 0; j < 8; j++) {
        const int m = mb + j * 16;
        int row = a0 + m;
        float4 x = (row < NG) ? ((const float4*)(g_pool2 + (size_t)row * 128))[c]
                              : make_float4(0.f, 0.f, 0.f, 0.f);
        split_store(x, sm + GS_A, m, c);
    }
    __syncthreads();

    float acc[4][8];
    #pragma unroll
    for (int a = 0; a < 4; a++)
        #pragma unroll
        for (int b = 0; b < 8; b++) acc[a][b] = 0.0f;
    mma_2pass(smb + GS_A, smb + GS_W, acc);

    float s0 = 0.0f, s1 = 0.0f;
    #pragma unroll
    for (int nb = 0; nb < 4; nb++) {
        #pragma unroll
        for (int g = 0; g < 2; g++) {
            const int n0 = wn * 64 + nb * 16 + g * 8 + (lane & 3) * 2;
            #pragma unroll
            for (int j = 0; j < 4; j++) {
                const int nn = n0 + (j & 1);
                float x = acc[nb][g * 4 + j] + sB[nn];
                float h = x / (1.0f + __expf(-x));
                float p = h * sV[nn];
                if (j < 2) s0 += p; else s1 += p;
            }
        }
    }
    s0 += __shfl_xor_sync(0xFFFFFFFF, s0, 1);
    s0 += __shfl_xor_sync(0xFFFFFFFF, s0, 2);
    s1 += __shfl_xor_sync(0xFFFFFFFF, s1, 1);
    s1 += __shfl_xor_sync(0xFFFFFFFF, s1, 2);
    if ((lane & 3) == 0) {
        const int mr = wm * 16 + (lane >> 2);
        sP[wn * 128 + mr] = s0;
        sP[wn * 128 + mr + 8] = s1;
    }
    __syncthreads();
    if (t < 128) {
        int row = a0 + t;
        if (row < NG) outS[row] = sP[t] + sP[128 + t] + b4[0];
    }
}

// ---------------------------------------------------------------------------
extern "C" void kernel_launch(void* const* d_in, const int* in_sizes, int n_in,
                              void* d_out, int out_size)
{
    const float* feat  = (const float*)d_in[0];
    const void*  batch = d_in[1];
    const float* W1 = (const float*)d_in[2];
    const float* b1 = (const float*)d_in[3];
    const float* W2 = (const float*)d_in[4];
    const float* b2 = (const float*)d_in[5];
    const float* W3 = (const float*)d_in[6];
    const float* b3 = (const float*)d_in[7];
    const float* W4 = (const float*)d_in[8];
    const float* b4 = (const float*)d_in[9];

    const int n = in_sizes[0] / DIMW;
    float* outS    = (float*)d_out;
    float* outFeat = (float*)d_out + NG;

    cudaFuncSetAttribute(kAtomTC, cudaFuncAttributeMaxDynamicSharedMemorySize, SMEM_ATOM);
    cudaFuncSetAttribute(kGraph1, cudaFuncAttributeMaxDynamicSharedMemorySize, SMEM_GRAPH);
    cudaFuncSetAttribute(kGraph2, cudaFuncAttributeMaxDynamicSharedMemorySize, SMEM_GRAPH);

    {
        size_t total = (size_t)NG * DIMW / 4 + NG;
        kZero<<<(int)((total + 255) / 256), 256>>>((const int*)batch, n);
    }
    kPrep<<<192, 256>>>(W1, W2, W3);
    {
        int ntiles = (n + 127) / 128;
        kAtomTC<<<296, 512, SMEM_ATOM>>>(feat, batch, n, b1, outFeat, ntiles);
    }
    {
        int grid = (NG + 127) / 128;
        kGraph1<<<grid, 512, SMEM_GRAPH>>>(b2);
        kGraph2<<<grid, 512, SMEM_GRAPH>>>(b3, W4, b4, outS);
    }
}

// round 11
// speedup vs baseline: 2.1776x; 1.0328x over previous
#include <cuda_runtime.h>
#include <cuda_fp16.h>
#include <math.h>
#include <stdint.h>

#define DIMW 128
#define NG   100000
#define AS_B 272              // bytes per fp16 row (128*2 + 16 pad)

// ---------------- scratch (no allocs) ----------------
__device__ float g_pool[(size_t)NG * DIMW];
__device__ float g_pool2[(size_t)NG * DIMW];
__device__ float g_cnt[NG];
__device__ int   g_is64;
__device__ __half g_WTh[3 * 128 * 128];   // W{1,2,3}^T fp16  [n][k]

// ---------------- kAtom smem layout (bytes) ----------------
#define SM_GID   0             // int[128] = 512
#define SM_B1    512           // float[128] = 512
#define SM_W     1024          // W fp16: 34816 -> ends 35840
#define SM_A     35840         // Ah 34816 ; sT (66048) reuses region -> ends 105472
#define SMEM_ATOM 105472

// ---------------- kGraph smem layout ----------------
#define GS_C     0             // cnt / sV : 512B
#define GS_B     512           // bias     : 512B
#define GS_P     1024          // partials : 1024B
#define GS_W     2048          // 34816 -> ends 36864
#define GS_A     36864         // Ah+Al 69632 -> ends 106496
#define SMEM_GRAPH 106496

__device__ __forceinline__ uint32_t smem_u32(const void* p) {
    uint32_t a;
    asm("{ .reg .u64 t; cvta.to.shared.u64 t, %1; cvt.u32.u64 %0, t; }" : "=r"(a) : "l"(p));
    return a;
}
__device__ __forceinline__ void ldsm4(uint32_t& r0, uint32_t& r1, uint32_t& r2, uint32_t& r3,
                                      uint32_t addr) {
    asm volatile("ldmatrix.sync.aligned.m8n8.x4.shared.b16 {%0,%1,%2,%3}, [%4];"
                 : "=r"(r0), "=r"(r1), "=r"(r2), "=r"(r3) : "r"(addr));
}
__device__ __forceinline__ void mma16816(float* c, const uint32_t* a, uint32_t b0, uint32_t b1) {
    asm volatile("mma.sync.aligned.m16n8k16.row.col.f32.f16.f16.f32 "
                 "{%0,%1,%2,%3}, {%4,%5,%6,%7}, {%8,%9}, {%0,%1,%2,%3};"
                 : "+f"(c[0]), "+f"(c[1]), "+f"(c[2]), "+f"(c[3])
                 : "r"(a[0]), "r"(a[1]), "r"(a[2]), "r"(a[3]), "r"(b0), "r"(b1));
}

// ---------------------------------------------------------------------------
// Warp-tile cores: 16 rows x 64 cols per warp, 16 warps cover 128x128.
// ---------------------------------------------------------------------------
// 1-pass: D = Ah @ Wh — used by kAtom
__device__ __forceinline__ void mma_1pass(uint32_t A, uint32_t W, float acc[4][8]) {
    const int t = threadIdx.x, w = t >> 5, lane = t & 31;
    const int wm = w >> 1, wn = w & 1;
    const int lm = lane & 7, q = lane >> 3;
    const uint32_t aOff = (uint32_t)((wm * 16 + lm + (q & 1) * 8) * AS_B + ((q >> 1) * 8) * 2);
    const uint32_t bOff = (uint32_t)((wn * 64 + lm + (q >> 1) * 8) * AS_B + ((q & 1) * 8) * 2);
    const uint32_t Ah = A + aOff, Bb = W + bOff;
    #pragma unroll
    for (int kk = 0; kk < 8; kk++) {
        uint32_t ah[4], b[4][4];
        ldsm4(ah[0], ah[1], ah[2], ah[3], Ah + kk * 32);
        #pragma unroll
        for (int nb = 0; nb < 4; nb++)
            ldsm4(b[nb][0], b[nb][1], b[nb][2], b[nb][3], Bb + nb * 16 * AS_B + kk * 32);
        #pragma unroll
        for (int nb = 0; nb < 4; nb++) {
            mma16816(acc[nb],     ah, b[nb][0], b[nb][1]);
            mma16816(acc[nb] + 4, ah, b[nb][2], b[nb][3]);
        }
    }
}
// 2-pass: D = (Ah + Al) @ Wh (exact A) — used by kGraph1/2
__device__ __forceinline__ void mma_2pass(uint32_t A, uint32_t W, float acc[4][8]) {
    const int t = threadIdx.x, w = t >> 5, lane = t & 31;
    const int wm = w >> 1, wn = w & 1;
    const int lm = lane & 7, q = lane >> 3;
    const uint32_t aOff = (uint32_t)((wm * 16 + lm + (q & 1) * 8) * AS_B + ((q >> 1) * 8) * 2);
    const uint32_t bOff = (uint32_t)((wn * 64 + lm + (q >> 1) * 8) * AS_B + ((q & 1) * 8) * 2);
    const uint32_t Ah = A + aOff, Al = A + 34816 + aOff, Bb = W + bOff;
    #pragma unroll
    for (int kk = 0; kk < 8; kk++) {
        uint32_t ah[4], al[4], b[4][4];
        ldsm4(ah[0], ah[1], ah[2], ah[3], Ah + kk * 32);
        ldsm4(al[0], al[1], al[2], al[3], Al + kk * 32);
        #pragma unroll
        for (int nb = 0; nb < 4; nb++)
            ldsm4(b[nb][0], b[nb][1], b[nb][2], b[nb][3], Bb + nb * 16 * AS_B + kk * 32);
        #pragma unroll
        for (int nb = 0; nb < 4; nb++) {
            mma16816(acc[nb],     ah, b[nb][0], b[nb][1]);
            mma16816(acc[nb] + 4, ah, b[nb][2], b[nb][3]);
        }
        #pragma unroll
        for (int nb = 0; nb < 4; nb++) {
            mma16816(acc[nb],     al, b[nb][0], b[nb][1]);
            mma16816(acc[nb] + 4, al, b[nb][2], b[nb][3]);
        }
    }
}

// stage one prepped fp16 weight matrix into padded smem (NT threads)
template <int NT>
__device__ __forceinline__ void stage_W(char* sm, uint32_t wOff, int widx, int t) {
    for (int i = t; i < 256; i += NT) {
        const int r = i >> 1, h = i & 1;
        const uint4* ws = (const uint4*)(g_WTh + widx * 16384 + r * 128 + h * 64);
        char* d = sm + wOff + r * AS_B + h * 128;
        #pragma unroll
        for (int j = 0; j < 8; j++) ((uint4*)d)[j] = ws[j];
    }
}

// fp16 round-only store (hi term) at (row m, float4-col c)
__device__ __forceinline__ void round_store(float4 x, char* dstH, int m, int c) {
    __half2 hp0 = __halves2half2(__float2half_rn(x.x), __float2half_rn(x.y));
    __half2 hp1 = __halves2half2(__float2half_rn(x.z), __float2half_rn(x.w));
    *(uint2*)(dstH + m * AS_B + c * 8) = make_uint2(*(uint32_t*)&hp0, *(uint32_t*)&hp1);
}
// fp16 hi/lo split store (exact A) at (row m, float4-col c)
__device__ __forceinline__ void split_store(float4 x, char* dstH, int m, int c) {
    __half h0 = __float2half_rn(x.x), h1 = __float2half_rn(x.y);
    __half h2 = __float2half_rn(x.z), h3 = __float2half_rn(x.w);
    __half l0 = __float2half_rn(x.x - __half2float(h0));
    __half l1 = __float2half_rn(x.y - __half2float(h1));
    __half l2 = __float2half_rn(x.z - __half2float(h2));
    __half l3 = __float2half_rn(x.w - __half2float(h3));
    __half2 hp0 = __halves2half2(h0, h1), hp1 = __halves2half2(h2, h3);
    __half2 lp0 = __halves2half2(l0, l1), lp1 = __halves2half2(l2, l3);
    *(uint2*)(dstH + m * AS_B + c * 8) = make_uint2(*(uint32_t*)&hp0, *(uint32_t*)&hp1);
    *(uint2*)(dstH + 34816 + m * AS_B + c * 8) = make_uint2(*(uint32_t*)&lp0, *(uint32_t*)&lp1);
}

// ---------------------------------------------------------------------------
// kInit: zero pool+cnt, detect batch dtype, prep fp16 weights (one launch)
// ---------------------------------------------------------------------------
__global__ void kInit(const int* __restrict__ batch32, int n,
                      const float* __restrict__ W1, const float* __restrict__ W2,
                      const float* __restrict__ W3) {
    size_t i = (size_t)blockIdx.x * blockDim.x + threadIdx.x;
    const size_t pool4 = (size_t)NG * DIMW / 4;
    if (i < pool4)
        ((float4*)g_pool)[i] = make_float4(0.f, 0.f, 0.f, 0.f);
    else if (i < pool4 + NG)
        g_cnt[i - pool4] = 0.0f;
    if (i < 3 * 16384) {
        int widx = (int)(i >> 14), e = (int)(i & 16383);
        int nn = e >> 7, kk = e & 127;
        const float* W = (widx == 0) ? W1 : (widx == 1) ? W2 : W3;
        g_WTh[i] = __float2half_rn(W[kk * 128 + nn]);
    }
    if (i == 0) g_is64 = (batch32[n - 1] == 0) ? 1 : 0;
}

// ---------------------------------------------------------------------------
// kAtomTC: persistent, 512 threads, 2 CTAs/SM, 1-pass fp16 core.
// Streaming hints keep g_pool resident in L2.
// ---------------------------------------------------------------------------
__global__ void __launch_bounds__(512, 2) kAtomTC(
    const float* __restrict__ feat, const void* __restrict__ batch, int n,
    const float* __restrict__ b1, float* __restrict__ outFeat, int ntiles)
{
    extern __shared__ char sm[];
    const uint32_t smb = smem_u32(sm);
    const int t = threadIdx.x, lane = t & 31, w = t >> 5;
    const int wm = w >> 1, wn = w & 1;
    const int is64 = g_is64;
    const int mb = t >> 5, c = t & 31;

    const int per = (ntiles + gridDim.x - 1) / gridDim.x;
    const int t0 = blockIdx.x * per;
    const int t1 = min(t0 + per, ntiles);
    if (t0 >= t1) return;

    if (t < 128) ((float*)(sm + SM_B1))[t] = b1[t];
    stage_W<512>(sm, SM_W, 0, t);
    __syncthreads();

    for (int i = t0; i < t1; ++i) {
        // 1) convert: streaming LDG -> fp16 round -> STS ; passthrough STG ; gids
        #pragma unroll
        for (int j = 0; j < 8; j++) {
            const int m = mb + j * 16;
            long long row = (long long)i * 128 + m;
            float4 x = make_float4(0.f, 0.f, 0.f, 0.f);
            if (row < n) {
                x = __ldcs(((const float4*)(feat + (size_t)row * 128)) + c);
                __stcs(((float4*)(outFeat + (size_t)row * 128)) + c, x);
            }
            round_store(x, sm + SM_A, m, c);
        }
        if (t < 128) {
            long long row = (long long)i * 128 + t;
            int g = -1;
            if (row < n)
                g = is64 ? (int)((const long long*)batch)[row] : ((const int*)batch)[row];
            ((int*)(sm + SM_GID))[t] = g;
        }
        __syncthreads();

        // 2) mma (1-pass)
        float acc[4][8];
        #pragma unroll
        for (int a = 0; a < 4; a++)
            #pragma unroll
            for (int b = 0; b < 8; b++) acc[a][b] = 0.0f;
        mma_1pass(smb + SM_A, smb + SM_W, acc);
        __syncthreads();   // all warps done reading A

        // 3) epilogue: bias + silu -> transposed sT (stride 129) in A region
        float* sT = (float*)(sm + SM_A);
        const float* sB1 = (const float*)(sm + SM_B1);
        #pragma unroll
        for (int nb = 0; nb < 4; nb++) {
            #pragma unroll
            for (int g = 0; g < 2; g++) {
                const int n0 = wn * 64 + nb * 16 + g * 8 + (lane & 3) * 2;
                const int r0 = wm * 16 + (lane >> 2);
                #pragma unroll
                for (int j = 0; j < 4; j++) {
                    const int nn = n0 + (j & 1);
                    const int mm = r0 + (j >> 1) * 8;
                    float x = acc[nb][g * 4 + j] + sB1[nn];
                    sT[nn * 129 + mm] = x / (1.0f + __expf(-x));
                }
            }
        }
        __syncthreads();

        // 4) run-length segment reduce (batch sorted); 4 quarters of 32 atoms
        const int d = t & 127, hh = t >> 7;
        const int mS = hh * 32, mE = mS + 32;
        const int* gid = (const int*)(sm + SM_GID);
        float run = 0.0f;
        int len = 0, cur = gid[mS];
        for (int mm = mS; mm < mE; ++mm) {
            int g = gid[mm];
            if (g != cur) {
                if (cur >= 0) {
                    atomicAdd(&g_pool[(size_t)cur * 128 + d], run);
                    if (d == 0) atomicAdd(&g_cnt[cur], (float)len);
                }
                run = 0.0f; len = 0; cur = g;
            }
            if (g >= 0) { run += sT[d * 129 + mm]; len++; }
        }
        if (cur >= 0) {
            atomicAdd(&g_pool[(size_t)cur * 128 + d], run);
            if (d == 0) atomicAdd(&g_cnt[cur], (float)len);
        }
        __syncthreads();   // reduce done before next convert overwrites sT/A
    }
}

// ---------------------------------------------------------------------------
// kGraph1: g_pool2 = g_pool @ W2 + cnt * b2   (2-pass, exact A, 2 CTAs/SM)
// ---------------------------------------------------------------------------
__global__ void __launch_bounds__(512, 2) kGraph1(const float* __restrict__ b2)
{
    extern __shared__ char sm[];
    const uint32_t smb = smem_u32(sm);
    const int t = threadIdx.x, lane = t & 31, w = t >> 5;
    const int wm = w >> 1, wn = w & 1;
    const int a0 = blockIdx.x * 128;
    const int mb = t >> 5, c = t & 31;

    float* sCnt = (float*)(sm + GS_C);
    float* sB   = (float*)(sm + GS_B);
    if (t < 128) {
        sCnt[t] = (a0 + t < NG) ? g_cnt[a0 + t] : 0.0f;
        sB[t] = b2[t];
    }
    stage_W<512>(sm, GS_W, 1, t);
    #pragma unroll
    for (int j = 0; j < 8; j++) {
        const int m = mb + j * 16;
        int row = a0 + m;
        float4 x = (row < NG) ? ((const float4*)(g_pool + (size_t)row * 128))[c]
                              : make_float4(0.f, 0.f, 0.f, 0.f);
        split_store(x, sm + GS_A, m, c);
    }
    __syncthreads();

    float acc[4][8];
    #pragma unroll
    for (int a = 0; a < 4; a++)
        #pragma unroll
        for (int b = 0; b < 8; b++) acc[a][b] = 0.0f;
    mma_2pass(smb + GS_A, smb + GS_W, acc);

    #pragma unroll
    for (int nb = 0; nb < 4; nb++) {
        #pragma unroll
        for (int g = 0; g < 2; g++) {
            const int n0 = wn * 64 + nb * 16 + g * 8 + (lane & 3) * 2;
            const int mr = wm * 16 + (lane >> 2);
            int row0 = a0 + mr, row1 = a0 + mr + 8;
            if (row0 < NG) {
                float cn = sCnt[mr];
                *(float2*)(g_pool2 + (size_t)row0 * 128 + n0) =
                    make_float2(acc[nb][g*4+0] + cn * sB[n0], acc[nb][g*4+1] + cn * sB[n0+1]);
            }
            if (row1 < NG) {
                float cn = sCnt[mr + 8];
                *(float2*)(g_pool2 + (size_t)row1 * 128 + n0) =
                    make_float2(acc[nb][g*4+2] + cn * sB[n0], acc[nb][g*4+3] + cn * sB[n0+1]);
            }
        }
    }
}

// ---------------------------------------------------------------------------
// kGraph2: out = silu(g_pool2 @ W3 + b3) @ W4 + b4   (2-pass, exact A, 2 CTAs/SM)
// ---------------------------------------------------------------------------
__global__ void __launch_bounds__(512, 2) kGraph2(
    const float* __restrict__ b3, const float* __restrict__ W4,
    const float* __restrict__ b4, float* __restrict__ outS)
{
    extern __shared__ char sm[];
    const uint32_t smb = smem_u32(sm);
    const int t = threadIdx.x, lane = t & 31, w = t >> 5;
    const int wm = w >> 1, wn = w & 1;
    const int a0 = blockIdx.x * 128;
    const int mb = t >> 5, c = t & 31;

    float* sV = (float*)(sm + GS_C);
    float* sB = (float*)(sm + GS_B);
    float* sP = (float*)(sm + GS_P);   // partials [2][128]
    if (t < 128) { sV[t] = W4[t]; sB[t] = b3[t]; }
    stage_W<512>(sm, GS_W, 2, t);
    #pragma unroll
    for (int j = 0; j < 8; j++) {
        const int m = mb + j * 16;
        int row = a0 + m;
        float4 x = (row < NG) ? ((const float4*)(g_pool2 + (size_t)row * 128))[c]
                              : make_float4(0.f, 0.f, 0.f, 0.f);
        split_store(x, sm + GS_A, m, c);
    }
    __syncthreads();

    float acc[4][8];
    #pragma unroll
    for (int a = 0; a < 4; a++)
        #pragma unroll
        for (int b = 0; b < 8; b++) acc[a][b] = 0.0f;
    mma_2pass(smb + GS_A, smb + GS_W, acc);

    float s0 = 0.0f, s1 = 0.0f;
    #pragma unroll
    for (int nb = 0; nb < 4; nb++) {
        #pragma unroll
        for (int g = 0; g < 2; g++) {
            const int n0 = wn * 64 + nb * 16 + g * 8 + (lane & 3) * 2;
            #pragma unroll
            for (int j = 0; j < 4; j++) {
                const int nn = n0 + (j & 1);
                float x = acc[nb][g * 4 + j] + sB[nn];
                float h = x / (1.0f + __expf(-x));
                float p = h * sV[nn];
                if (j < 2) s0 += p; else s1 += p;
            }
        }
    }
    s0 += __shfl_xor_sync(0xFFFFFFFF, s0, 1);
    s0 += __shfl_xor_sync(0xFFFFFFFF, s0, 2);
    s1 += __shfl_xor_sync(0xFFFFFFFF, s1, 1);
    s1 += __shfl_xor_sync(0xFFFFFFFF, s1, 2);
    if ((lane & 3) == 0) {
        const int mr = wm * 16 + (lane >> 2);
        sP[wn * 128 + mr] = s0;
        sP[wn * 128 + mr + 8] = s1;
    }
    __syncthreads();
    if (t < 128) {
        int row = a0 + t;
        if (row < NG) outS[row] = sP[t] + sP[128 + t] + b4[0];
    }
}

// ---------------------------------------------------------------------------
extern "C" void kernel_launch(void* const* d_in, const int* in_sizes, int n_in,
                              void* d_out, int out_size)
{
    const float* feat  = (const float*)d_in[0];
    const void*  batch = d_in[1];
    const float* W1 = (const float*)d_in[2];
    const float* b1 = (const float*)d_in[3];
    const float* W2 = (const float*)d_in[4];
    const float* b2 = (const float*)d_in[5];
    const float* W3 = (const float*)d_in[6];
    const float* b3 = (const float*)d_in[7];
    const float* W4 = (const float*)d_in[8];
    const float* b4 = (const float*)d_in[9];

    const int n = in_sizes[0] / DIMW;
    float* outS    = (float*)d_out;
    float* outFeat = (float*)d_out + NG;

    cudaFuncSetAttribute(kAtomTC, cudaFuncAttributeMaxDynamicSharedMemorySize, SMEM_ATOM);
    cudaFuncSetAttribute(kGraph1, cudaFuncAttributeMaxDynamicSharedMemorySize, SMEM_GRAPH);
    cudaFuncSetAttribute(kGraph2, cudaFuncAttributeMaxDynamicSharedMemorySize, SMEM_GRAPH);

    {
        size_t total = (size_t)NG * DIMW / 4 + NG;
        kInit<<<(int)((total + 255) / 256), 256>>>((const int*)batch, n, W1, W2, W3);
    }
    {
        int ntiles = (n + 127) / 128;
        kAtomTC<<<296, 512, SMEM_ATOM>>>(feat, batch, n, b1, outFeat, ntiles);
    }
    {
        int grid = (NG + 127) / 128;
        kGraph1<<<grid, 512, SMEM_GRAPH>>>(b2);
        kGraph2<<<grid, 512, SMEM_GRAPH>>>(b3, W4, b4, outS);
    }
}